// round 1
// baseline (speedup 1.0000x reference)
#include <cuda_runtime.h>
#include <math.h>

#define S 4096
#define H 1152
#define NH 16
#define HD 72
#define FF 4304
#define LN_EPS 1e-6f

// ---------------- scratch (allocation-free: device globals) ----------------
__device__ float g_xn[S * H];
__device__ float g_q[S * H];
__device__ float g_k[S * H];
__device__ float g_v[S * H];
__device__ float g_attn[S * H];
__device__ float g_hid[S * H];
__device__ float g_y[S * H];
__device__ float g_ff[(size_t)S * FF];
__device__ int g_segs[S];
__device__ int g_sege[S];

// ---------------- LayerNorm: one block per row ----------------
__global__ __launch_bounds__(256) void ln_kernel(const float* __restrict__ x,
                                                 const float* __restrict__ g,
                                                 const float* __restrict__ b,
                                                 float* __restrict__ y) {
    int row = blockIdx.x;
    const float* xr = x + (size_t)row * H;
    __shared__ float red[256];
    int tid = threadIdx.x;

    float s = 0.f;
    for (int i = tid; i < H; i += 256) s += xr[i];
    red[tid] = s;
    __syncthreads();
    for (int off = 128; off > 0; off >>= 1) {
        if (tid < off) red[tid] += red[tid + off];
        __syncthreads();
    }
    float mu = red[0] * (1.0f / H);
    __syncthreads();

    float sq = 0.f;
    for (int i = tid; i < H; i += 256) {
        float d = xr[i] - mu;
        sq += d * d;
    }
    red[tid] = sq;
    __syncthreads();
    for (int off = 128; off > 0; off >>= 1) {
        if (tid < off) red[tid] += red[tid + off];
        __syncthreads();
    }
    float inv = rsqrtf(red[0] * (1.0f / H) + LN_EPS);

    float* yr = y + (size_t)row * H;
    for (int i = tid; i < H; i += 256)
        yr[i] = (xr[i] - mu) * inv * g[i] + b[i];
}

// ---------------- document segment ranges (ids are sorted) ----------------
__global__ void doc_ranges(const int* __restrict__ ids, int* __restrict__ segs,
                           int* __restrict__ sege) {
    int i = blockIdx.x * blockDim.x + threadIdx.x;
    if (i >= S) return;
    int d = ids[i];
    int lo = 0, hi = S;
    while (lo < hi) { int mid = (lo + hi) >> 1; if (ids[mid] < d) lo = mid + 1; else hi = mid; }
    segs[i] = lo;
    lo = 0; hi = S;
    while (lo < hi) { int mid = (lo + hi) >> 1; if (ids[mid] <= d) lo = mid + 1; else hi = mid; }
    sege[i] = lo;
}

// ---------------- tiled SGEMM: C[M,N] = A[M,K] @ W[N,K]^T + epilogue -------
// epi: 0 = +bias ; 1 = +bias then tanh-GELU ; 2 = +bias + res
#define BM 64
#define BN 64
#define BK 16

__global__ __launch_bounds__(256) void sgemm(const float* __restrict__ A,
                                             const float* __restrict__ W,
                                             const float* __restrict__ bias,
                                             const float* __restrict__ res,
                                             float* __restrict__ C,
                                             int M, int N, int K, int epi) {
    __shared__ float As[BK][BM];
    __shared__ float Ws[BK][BN];

    int tid = threadIdx.x;
    int tx = tid & 15;        // 0..15  -> N direction (4 cols each)
    int ty = tid >> 4;        // 0..15  -> M direction (4 rows each)
    int m0 = blockIdx.y * BM;
    int n0 = blockIdx.x * BN;

    int lr = tid >> 2;        // 0..63 tile row for loading
    int lc = (tid & 3) * 4;   // 0,4,8,12 k-offset for loading (float4)

    float acc[4][4] = {};

    int nk = K / BK;          // K is always a multiple of 16 here
    for (int t = 0; t < nk; ++t) {
        // stage A tile (transposed into smem)
        const float4 av = *(const float4*)(A + (size_t)(m0 + lr) * K + t * BK + lc);
        As[lc + 0][lr] = av.x; As[lc + 1][lr] = av.y;
        As[lc + 2][lr] = av.z; As[lc + 3][lr] = av.w;
        // stage W tile (guard N for FF=4304)
        int wr = n0 + lr;
        float4 wv = make_float4(0.f, 0.f, 0.f, 0.f);
        if (wr < N) wv = *(const float4*)(W + (size_t)wr * K + t * BK + lc);
        Ws[lc + 0][lr] = wv.x; Ws[lc + 1][lr] = wv.y;
        Ws[lc + 2][lr] = wv.z; Ws[lc + 3][lr] = wv.w;
        __syncthreads();

#pragma unroll
        for (int kk = 0; kk < BK; ++kk) {
            float4 a4 = *(const float4*)&As[kk][ty * 4];
            float4 b4 = *(const float4*)&Ws[kk][tx * 4];
            float a[4] = {a4.x, a4.y, a4.z, a4.w};
            float b[4] = {b4.x, b4.y, b4.z, b4.w};
#pragma unroll
            for (int i = 0; i < 4; ++i)
#pragma unroll
                for (int j = 0; j < 4; ++j)
                    acc[i][j] = fmaf(a[i], b[j], acc[i][j]);
        }
        __syncthreads();
    }

#pragma unroll
    for (int i = 0; i < 4; ++i) {
        int m = m0 + ty * 4 + i;
#pragma unroll
        for (int j = 0; j < 4; ++j) {
            int n = n0 + tx * 4 + j;
            if (n >= N) continue;
            float v = acc[i][j] + bias[n];
            if (epi == 1) {
                float t = tanhf(0.7978845608028654f * (v + 0.044715f * v * v * v));
                v = 0.5f * v * (1.0f + t);
            } else if (epi == 2) {
                v += res[(size_t)m * N + n];
            }
            C[(size_t)m * N + n] = v;
        }
    }
}

// ---------------- segment-restricted attention ----------------
// one block (128 threads) per (query, head); online softmax over the query's
// document segment, chunked by 128 keys.
#define ACH 128

__global__ __launch_bounds__(ACH) void attn_kernel(const float* __restrict__ Q,
                                                   const float* __restrict__ Km,
                                                   const float* __restrict__ V,
                                                   const int* __restrict__ segs,
                                                   const int* __restrict__ sege,
                                                   float* __restrict__ O) {
    int q = blockIdx.x;
    int h = blockIdx.y;
    int tid = threadIdx.x;

    __shared__ float qv[HD];
    __shared__ float sc[ACH];
    __shared__ float red[ACH];

    const float scale = 0.11785113019775793f;  // 72^-0.5
    const float NEGINF = -__int_as_float(0x7f800000) * 0.0f - 3.0e38f; // large negative

    const float* qp = Q + (size_t)q * H + h * HD;
    if (tid < HD) qv[tid] = qp[tid];

    int s0 = segs[q], s1 = sege[q];
    float acc = 0.f;          // output dim `tid` (tid < HD)
    float m = -3.0e38f, l = 0.f;
    (void)NEGINF;
    __syncthreads();

    for (int c0 = s0; c0 < s1; c0 += ACH) {
        int len = min(ACH, s1 - c0);

        float s = -3.0e38f;
        if (tid < len) {
            const float* kp = Km + (size_t)(c0 + tid) * H + h * HD;
            float dot = 0.f;
#pragma unroll 8
            for (int d = 0; d < HD; ++d) dot = fmaf(qv[d], kp[d], dot);
            s = dot * scale;
        }
        // block max
        red[tid] = s;
        __syncthreads();
        for (int off = 64; off > 0; off >>= 1) {
            if (tid < off) red[tid] = fmaxf(red[tid], red[tid + off]);
            __syncthreads();
        }
        float mnew = fmaxf(m, red[0]);
        __syncthreads();

        float p = (tid < len) ? __expf(s - mnew) : 0.f;
        sc[tid] = p;
        red[tid] = p;
        __syncthreads();
        for (int off = 64; off > 0; off >>= 1) {
            if (tid < off) red[tid] += red[tid + off];
            __syncthreads();
        }
        float corr = __expf(m - mnew);
        l = l * corr + red[0];
        m = mnew;

        if (tid < HD) {
            acc *= corr;
            const float* vb = V + (size_t)c0 * H + h * HD + tid;
            for (int j = 0; j < len; ++j)
                acc = fmaf(sc[j], vb[(size_t)j * H], acc);
        }
        __syncthreads();
    }

    if (tid < HD) O[(size_t)q * H + h * HD + tid] = acc / l;
}

// ---------------- launch ----------------
extern "C" void kernel_launch(void* const* d_in, const int* in_sizes, int n_in,
                              void* d_out, int out_size) {
    const float* hs    = (const float*)d_in[0];
    const int*   doc   = (const int*)d_in[1];
    const float* q_w   = (const float*)d_in[2];
    const float* q_b   = (const float*)d_in[3];
    const float* k_w   = (const float*)d_in[4];
    const float* k_b   = (const float*)d_in[5];
    const float* v_w   = (const float*)d_in[6];
    const float* v_b   = (const float*)d_in[7];
    const float* o_w   = (const float*)d_in[8];
    const float* o_b   = (const float*)d_in[9];
    const float* ln1_g = (const float*)d_in[10];
    const float* ln1_b = (const float*)d_in[11];
    const float* ln2_g = (const float*)d_in[12];
    const float* ln2_b = (const float*)d_in[13];
    const float* fc1_w = (const float*)d_in[14];
    const float* fc1_b = (const float*)d_in[15];
    const float* fc2_w = (const float*)d_in[16];
    const float* fc2_b = (const float*)d_in[17];
    float* out = (float*)d_out;

    float *xn, *q, *k, *v, *attn, *hid, *y, *ff;
    int *segs, *sege;
    cudaGetSymbolAddress((void**)&xn,   g_xn);
    cudaGetSymbolAddress((void**)&q,    g_q);
    cudaGetSymbolAddress((void**)&k,    g_k);
    cudaGetSymbolAddress((void**)&v,    g_v);
    cudaGetSymbolAddress((void**)&attn, g_attn);
    cudaGetSymbolAddress((void**)&hid,  g_hid);
    cudaGetSymbolAddress((void**)&y,    g_y);
    cudaGetSymbolAddress((void**)&ff,   g_ff);
    cudaGetSymbolAddress((void**)&segs, g_segs);
    cudaGetSymbolAddress((void**)&sege, g_sege);

    dim3 gH((H + BN - 1) / BN, S / BM);   // N=1152 GEMMs
    dim3 gF((FF + BN - 1) / BN, S / BM);  // N=4304 GEMM

    ln_kernel<<<S, 256>>>(hs, ln1_g, ln1_b, xn);
    doc_ranges<<<(S + 255) / 256, 256>>>(doc, segs, sege);

    sgemm<<<gH, 256>>>(xn, q_w, q_b, nullptr, q, S, H, H, 0);
    sgemm<<<gH, 256>>>(xn, k_w, k_b, nullptr, k, S, H, H, 0);
    sgemm<<<gH, 256>>>(xn, v_w, v_b, nullptr, v, S, H, H, 0);

    attn_kernel<<<dim3(S, NH), ACH>>>(q, k, v, segs, sege, attn);

    sgemm<<<gH, 256>>>(attn, o_w, o_b, hs, hid, S, H, H, 2);

    ln_kernel<<<S, 256>>>(hid, ln2_g, ln2_b, y);

    sgemm<<<gF, 256>>>(y, fc1_w, fc1_b, nullptr, ff, S, FF, H, 1);
    sgemm<<<gH, 256>>>(ff, fc2_w, fc2_b, hid, out, S, H, FF, 2);
}

// round 2
// speedup vs baseline: 3.8302x; 3.8302x over previous
#include <cuda_runtime.h>
#include <math.h>
#include <stdint.h>

#define S 4096
#define H 1152
#define NH 16
#define HD 72
#define FF 4304
#define LN_EPS 1e-6f

// ---------------- scratch (allocation-free: device globals) ----------------
__device__ float g_xn[S * H];
__device__ float g_q[S * H];
__device__ float g_k[S * H];
__device__ float g_v[S * H];
__device__ float g_attn[S * H];
__device__ float g_hid[S * H];
__device__ float g_y[S * H];
__device__ float g_ff[(size_t)S * FF];
__device__ int g_segs[S];
__device__ int g_sege[S];

// ---------------- LayerNorm: one block per row ----------------
__global__ __launch_bounds__(256) void ln_kernel(const float* __restrict__ x,
                                                 const float* __restrict__ g,
                                                 const float* __restrict__ b,
                                                 float* __restrict__ y) {
    int row = blockIdx.x;
    const float* xr = x + (size_t)row * H;
    __shared__ float red[256];
    int tid = threadIdx.x;

    float s = 0.f;
    for (int i = tid; i < H; i += 256) s += xr[i];
    red[tid] = s;
    __syncthreads();
    for (int off = 128; off > 0; off >>= 1) {
        if (tid < off) red[tid] += red[tid + off];
        __syncthreads();
    }
    float mu = red[0] * (1.0f / H);
    __syncthreads();

    float sq = 0.f;
    for (int i = tid; i < H; i += 256) {
        float d = xr[i] - mu;
        sq += d * d;
    }
    red[tid] = sq;
    __syncthreads();
    for (int off = 128; off > 0; off >>= 1) {
        if (tid < off) red[tid] += red[tid + off];
        __syncthreads();
    }
    float inv = rsqrtf(red[0] * (1.0f / H) + LN_EPS);

    float* yr = y + (size_t)row * H;
    for (int i = tid; i < H; i += 256)
        yr[i] = (xr[i] - mu) * inv * g[i] + b[i];
}

// ---------------- document segment ranges (ids are sorted) ----------------
__global__ void doc_ranges(const int* __restrict__ ids, int* __restrict__ segs,
                           int* __restrict__ sege) {
    int i = blockIdx.x * blockDim.x + threadIdx.x;
    if (i >= S) return;
    int d = ids[i];
    int lo = 0, hi = S;
    while (lo < hi) { int mid = (lo + hi) >> 1; if (ids[mid] < d) lo = mid + 1; else hi = mid; }
    segs[i] = lo;
    lo = 0; hi = S;
    while (lo < hi) { int mid = (lo + hi) >> 1; if (ids[mid] <= d) lo = mid + 1; else hi = mid; }
    sege[i] = lo;
}

// ---------------- TF32 tensor-core GEMM ----------------
// C[M,N] = A[M,K] @ W[N,K]^T + epilogue. epi: 0=+bias, 1=+bias+gelu, 2=+bias+res
#define BM 128
#define BN 64
#define BK 16
#define BKP 20   // padded smem pitch (floats): conflict-free fragment loads

__device__ __forceinline__ uint32_t f2tf(float x) {
    uint32_t r;
    asm("cvt.rna.tf32.f32 %0, %1;" : "=r"(r) : "f"(x));
    return r;
}

__device__ __forceinline__ void mma_tf32(float* c, const uint32_t* a, const uint32_t* b) {
    asm volatile(
        "mma.sync.aligned.m16n8k8.row.col.f32.tf32.tf32.f32 "
        "{%0,%1,%2,%3}, {%4,%5,%6,%7}, {%8,%9}, {%0,%1,%2,%3};"
        : "+f"(c[0]), "+f"(c[1]), "+f"(c[2]), "+f"(c[3])
        : "r"(a[0]), "r"(a[1]), "r"(a[2]), "r"(a[3]), "r"(b[0]), "r"(b[1]));
}

__device__ __forceinline__ void cp16(void* dst, const void* src, bool valid) {
    uint32_t d = (uint32_t)__cvta_generic_to_shared(dst);
    int sz = valid ? 16 : 0;
    asm volatile("cp.async.cg.shared.global [%0], [%1], 16, %2;\n"
                 :: "r"(d), "l"(src), "r"(sz));
}

__global__ __launch_bounds__(256) void gemm_tf32(const float* __restrict__ A,
                                                 const float* __restrict__ W,
                                                 const float* __restrict__ bias,
                                                 const float* __restrict__ res,
                                                 float* __restrict__ C,
                                                 int M, int N, int K, int epi) {
    __shared__ float As[2][BM][BKP];
    __shared__ float Ws[2][BN][BKP];

    int tid = threadIdx.x;
    int lane = tid & 31, warp = tid >> 5;
    int wm = warp & 3;        // 4 warps along M -> 32 rows each
    int wn = warp >> 2;       // 2 warps along N -> 32 cols each
    int m0 = blockIdx.y * BM;
    int n0 = blockIdx.x * BN;

    int lrow = tid >> 2;          // 0..63
    int lch = (tid & 3) * 4;      // float offset {0,4,8,12}

    float acc[2][4][4];
#pragma unroll
    for (int i = 0; i < 2; ++i)
#pragma unroll
        for (int j = 0; j < 4; ++j)
#pragma unroll
            for (int l = 0; l < 4; ++l) acc[i][j][l] = 0.f;

    int nk = K / BK;

    // prologue: stage tile 0
    {
        const float* Ab = A + (size_t)m0 * K + lch;
        cp16(&As[0][lrow][lch],      Ab + (size_t)lrow * K,        true);
        cp16(&As[0][lrow + 64][lch], Ab + (size_t)(lrow + 64) * K, true);
        cp16(&Ws[0][lrow][lch], W + (size_t)(n0 + lrow) * K + lch, (n0 + lrow) < N);
    }
    asm volatile("cp.async.commit_group;\n" ::: "memory");

    int fr = lane >> 2;   // fragment row-in-group
    int fc = lane & 3;    // fragment col-in-group

    for (int t = 0; t < nk; ++t) {
        asm volatile("cp.async.wait_group 0;\n" ::: "memory");
        __syncthreads();

        int st = t & 1;
        if (t + 1 < nk) {
            int ko = (t + 1) * BK + lch;
            const float* Ab = A + (size_t)m0 * K + ko;
            cp16(&As[st ^ 1][lrow][lch],      Ab + (size_t)lrow * K,        true);
            cp16(&As[st ^ 1][lrow + 64][lch], Ab + (size_t)(lrow + 64) * K, true);
            cp16(&Ws[st ^ 1][lrow][lch], W + (size_t)(n0 + lrow) * K + ko, (n0 + lrow) < N);
        }
        asm volatile("cp.async.commit_group;\n" ::: "memory");

#pragma unroll
        for (int kk = 0; kk < 2; ++kk) {
            int kb = kk * 8;
            uint32_t a[2][4], b[4][2];
#pragma unroll
            for (int mt = 0; mt < 2; ++mt) {
                int mr = wm * 32 + mt * 16;
                a[mt][0] = f2tf(As[st][mr + fr][kb + fc]);
                a[mt][1] = f2tf(As[st][mr + fr + 8][kb + fc]);
                a[mt][2] = f2tf(As[st][mr + fr][kb + fc + 4]);
                a[mt][3] = f2tf(As[st][mr + fr + 8][kb + fc + 4]);
            }
#pragma unroll
            for (int nt = 0; nt < 4; ++nt) {
                int nr = wn * 32 + nt * 8;
                b[nt][0] = f2tf(Ws[st][nr + fr][kb + fc]);
                b[nt][1] = f2tf(Ws[st][nr + fr][kb + fc + 4]);
            }
#pragma unroll
            for (int mt = 0; mt < 2; ++mt)
#pragma unroll
                for (int nt = 0; nt < 4; ++nt)
                    mma_tf32(acc[mt][nt], a[mt], b[nt]);
        }
    }

    // epilogue
#pragma unroll
    for (int mt = 0; mt < 2; ++mt) {
        int row = m0 + wm * 32 + mt * 16 + fr;
#pragma unroll
        for (int nt = 0; nt < 4; ++nt) {
            int col = n0 + wn * 32 + nt * 8 + fc * 2;
#pragma unroll
            for (int l = 0; l < 4; ++l) {
                int r = row + ((l >> 1) ? 8 : 0);
                int c = col + (l & 1);
                if (c >= N) continue;
                float v = acc[mt][nt][l] + bias[c];
                if (epi == 1) {
                    float u = 0.7978845608028654f * (v + 0.044715f * v * v * v);
                    float e = __expf(2.f * u);
                    float th = 1.f - 2.f / (e + 1.f);
                    v = 0.5f * v * (1.0f + th);
                } else if (epi == 2) {
                    v += res[(size_t)r * N + c];
                }
                C[(size_t)r * N + c] = v;
            }
        }
    }
}

// ---------------- tiled document-masked attention ----------------
// block = 256 threads, grid (S/64, NH). Each block: 64 queries x 1 head.
// Warp w owns query rows w*8..w*8+7. K/V chunks of 64 in smem (pitch 73).
#define QT 64
#define KT 64
#define KP 73
#define PP 65

__global__ __launch_bounds__(256) void attn_tile(const float* __restrict__ Q,
                                                 const float* __restrict__ Km,
                                                 const float* __restrict__ V,
                                                 const int* __restrict__ segs,
                                                 const int* __restrict__ sege,
                                                 float* __restrict__ O) {
    extern __shared__ float sm[];
    float* Qs = sm;                 // QT*KP
    float* Ks = Qs + QT * KP;       // KT*KP
    float* Vs = Ks + KT * KP;       // KT*KP
    float* Ps = Vs + KT * KP;       // QT*PP

    int h = blockIdx.y;
    int q0 = blockIdx.x * QT;
    int tid = threadIdx.x, lane = tid & 31, warp = tid >> 5;
    const float scale = 0.11785113019775793f;   // 72^-0.5

    // stage Q tile
    for (int idx = tid; idx < QT * HD; idx += 256) {
        int r = idx / HD, d = idx - r * HD;
        Qs[r * KP + d] = Q[(size_t)(q0 + r) * H + h * HD + d];
    }

    int s0[8], s1[8];
    float mrow[8], lrow[8], o[8][3];
#pragma unroll
    for (int i = 0; i < 8; ++i) {
        int qg = q0 + warp * 8 + i;
        s0[i] = segs[qg];
        s1[i] = sege[qg];
        mrow[i] = -3.0e38f;
        lrow[i] = 0.f;
        o[i][0] = o[i][1] = o[i][2] = 0.f;
    }

    int kstart = segs[q0];
    int kend = sege[q0 + QT - 1];
    int d2ok = (lane + 64 < HD);

    for (int c0 = kstart; c0 < kend; c0 += KT) {
        int len = min(KT, kend - c0);
        __syncthreads();   // previous chunk fully consumed
        for (int idx = tid; idx < KT * HD; idx += 256) {
            int r = idx / HD, d = idx - r * HD;
            float kv = 0.f, vv = 0.f;
            if (r < len) {
                size_t g = (size_t)(c0 + r) * H + h * HD + d;
                kv = Km[g];
                vv = V[g];
            }
            Ks[r * KP + d] = kv;
            Vs[r * KP + d] = vv;
        }
        __syncthreads();

        // scores: lane covers keys {lane, lane+32} for 8 q rows
        float sc[8][2];
#pragma unroll
        for (int i = 0; i < 8; ++i) { sc[i][0] = 0.f; sc[i][1] = 0.f; }
        const float* qb = Qs + (warp * 8) * KP;
        for (int d = 0; d < HD; ++d) {
            float k0v = Ks[lane * KP + d];
            float k1v = Ks[(lane + 32) * KP + d];
#pragma unroll
            for (int i = 0; i < 8; ++i) {
                float qd = qb[i * KP + d];
                sc[i][0] = fmaf(qd, k0v, sc[i][0]);
                sc[i][1] = fmaf(qd, k1v, sc[i][1]);
            }
        }

        int kg0 = c0 + lane, kg1 = c0 + lane + 32;
#pragma unroll
        for (int i = 0; i < 8; ++i) {
            bool v0ok = (kg0 >= s0[i]) && (kg0 < s1[i]);
            bool v1ok = (kg1 >= s0[i]) && (kg1 < s1[i]);
            float v0 = v0ok ? sc[i][0] * scale : -3.0e38f;
            float v1 = v1ok ? sc[i][1] * scale : -3.0e38f;
            float mx = fmaxf(v0, v1);
#pragma unroll
            for (int ofs = 16; ofs > 0; ofs >>= 1)
                mx = fmaxf(mx, __shfl_xor_sync(0xffffffffu, mx, ofs));
            float mnew = fmaxf(mrow[i], mx);
            float p0 = v0ok ? __expf(v0 - mnew) : 0.f;
            float p1 = v1ok ? __expf(v1 - mnew) : 0.f;
            float ps = p0 + p1;
#pragma unroll
            for (int ofs = 16; ofs > 0; ofs >>= 1)
                ps += __shfl_xor_sync(0xffffffffu, ps, ofs);
            float corr = __expf(mrow[i] - mnew);
            lrow[i] = lrow[i] * corr + ps;
            mrow[i] = mnew;
            o[i][0] *= corr; o[i][1] *= corr; o[i][2] *= corr;
            Ps[(warp * 8 + i) * PP + lane] = p0;
            Ps[(warp * 8 + i) * PP + lane + 32] = p1;
        }
        __syncwarp();

        // V accumulation: lane owns dims {lane, lane+32, lane+64}
        for (int k = 0; k < len; ++k) {
            float vv0 = Vs[k * KP + lane];
            float vv1 = Vs[k * KP + lane + 32];
            float vv2 = d2ok ? Vs[k * KP + lane + 64] : 0.f;
#pragma unroll
            for (int i = 0; i < 8; ++i) {
                float p = Ps[(warp * 8 + i) * PP + k];
                o[i][0] = fmaf(p, vv0, o[i][0]);
                o[i][1] = fmaf(p, vv1, o[i][1]);
                o[i][2] = fmaf(p, vv2, o[i][2]);
            }
        }
    }

#pragma unroll
    for (int i = 0; i < 8; ++i) {
        float inv = 1.f / lrow[i];
        size_t base = (size_t)(q0 + warp * 8 + i) * H + h * HD;
        O[base + lane] = o[i][0] * inv;
        O[base + lane + 32] = o[i][1] * inv;
        if (d2ok) O[base + lane + 64] = o[i][2] * inv;
    }
}

// ---------------- launch ----------------
extern "C" void kernel_launch(void* const* d_in, const int* in_sizes, int n_in,
                              void* d_out, int out_size) {
    const float* hs    = (const float*)d_in[0];
    const int*   doc   = (const int*)d_in[1];
    const float* q_w   = (const float*)d_in[2];
    const float* q_b   = (const float*)d_in[3];
    const float* k_w   = (const float*)d_in[4];
    const float* k_b   = (const float*)d_in[5];
    const float* v_w   = (const float*)d_in[6];
    const float* v_b   = (const float*)d_in[7];
    const float* o_w   = (const float*)d_in[8];
    const float* o_b   = (const float*)d_in[9];
    const float* ln1_g = (const float*)d_in[10];
    const float* ln1_b = (const float*)d_in[11];
    const float* ln2_g = (const float*)d_in[12];
    const float* ln2_b = (const float*)d_in[13];
    const float* fc1_w = (const float*)d_in[14];
    const float* fc1_b = (const float*)d_in[15];
    const float* fc2_w = (const float*)d_in[16];
    const float* fc2_b = (const float*)d_in[17];
    float* out = (float*)d_out;

    float *xn, *q, *k, *v, *attn, *hid, *y, *ff;
    int *segs, *sege;
    cudaGetSymbolAddress((void**)&xn,   g_xn);
    cudaGetSymbolAddress((void**)&q,    g_q);
    cudaGetSymbolAddress((void**)&k,    g_k);
    cudaGetSymbolAddress((void**)&v,    g_v);
    cudaGetSymbolAddress((void**)&attn, g_attn);
    cudaGetSymbolAddress((void**)&hid,  g_hid);
    cudaGetSymbolAddress((void**)&y,    g_y);
    cudaGetSymbolAddress((void**)&ff,   g_ff);
    cudaGetSymbolAddress((void**)&segs, g_segs);
    cudaGetSymbolAddress((void**)&sege, g_sege);

    int att_smem = (QT * KP + 2 * KT * KP + QT * PP) * (int)sizeof(float);
    static bool attr_set = false;
    if (!attr_set) {
        cudaFuncSetAttribute(attn_tile, cudaFuncAttributeMaxDynamicSharedMemorySize, att_smem);
        attr_set = true;
    }

    dim3 gH(H / BN, S / BM);                 // (18, 32)
    dim3 gF((FF + BN - 1) / BN, S / BM);     // (68, 32)

    ln_kernel<<<S, 256>>>(hs, ln1_g, ln1_b, xn);
    doc_ranges<<<(S + 255) / 256, 256>>>(doc, segs, sege);

    gemm_tf32<<<gH, 256>>>(xn, q_w, q_b, nullptr, q, S, H, H, 0);
    gemm_tf32<<<gH, 256>>>(xn, k_w, k_b, nullptr, k, S, H, H, 0);
    gemm_tf32<<<gH, 256>>>(xn, v_w, v_b, nullptr, v, S, H, H, 0);

    attn_tile<<<dim3(S / QT, NH), 256, att_smem>>>(q, k, v, segs, sege, attn);

    gemm_tf32<<<gH, 256>>>(attn, o_w, o_b, hs, hid, S, H, H, 2);

    ln_kernel<<<S, 256>>>(hid, ln2_g, ln2_b, y);

    gemm_tf32<<<gF, 256>>>(y, fc1_w, fc1_b, nullptr, ff, S, FF, H, 1);
    gemm_tf32<<<gH, 256>>>(ff, fc2_w, fc2_b, hid, out, S, H, FF, 2);
}

// round 3
// speedup vs baseline: 4.1330x; 1.0791x over previous
#include <cuda_runtime.h>
#include <math.h>
#include <stdint.h>

#define S 4096
#define H 1152
#define NH 16
#define HD 72
#define FF 4304
#define LN_EPS 1e-6f

// ---------------- scratch (allocation-free: device globals) ----------------
__device__ float g_xn[S * H];
__device__ float g_q[S * H];
__device__ float g_k[S * H];
__device__ float g_v[S * H];
__device__ float g_attn[S * H];
__device__ float g_hid[S * H];
__device__ float g_y[S * H];
__device__ float g_ff[(size_t)S * FF];
__device__ int g_segs[S];
__device__ int g_sege[S];

// ---------------- LayerNorm: one block per row ----------------
__global__ __launch_bounds__(256) void ln_kernel(const float* __restrict__ x,
                                                 const float* __restrict__ g,
                                                 const float* __restrict__ b,
                                                 float* __restrict__ y) {
    int row = blockIdx.x;
    const float* xr = x + (size_t)row * H;
    __shared__ float red[256];
    int tid = threadIdx.x;

    float s = 0.f;
    for (int i = tid; i < H; i += 256) s += xr[i];
    red[tid] = s;
    __syncthreads();
    for (int off = 128; off > 0; off >>= 1) {
        if (tid < off) red[tid] += red[tid + off];
        __syncthreads();
    }
    float mu = red[0] * (1.0f / H);
    __syncthreads();

    float sq = 0.f;
    for (int i = tid; i < H; i += 256) {
        float d = xr[i] - mu;
        sq += d * d;
    }
    red[tid] = sq;
    __syncthreads();
    for (int off = 128; off > 0; off >>= 1) {
        if (tid < off) red[tid] += red[tid + off];
        __syncthreads();
    }
    float inv = rsqrtf(red[0] * (1.0f / H) + LN_EPS);

    float* yr = y + (size_t)row * H;
    for (int i = tid; i < H; i += 256)
        yr[i] = (xr[i] - mu) * inv * g[i] + b[i];
}

// ---------------- document segment ranges (ids are sorted) ----------------
__global__ void doc_ranges(const int* __restrict__ ids, int* __restrict__ segs,
                           int* __restrict__ sege) {
    int i = blockIdx.x * blockDim.x + threadIdx.x;
    if (i >= S) return;
    int d = ids[i];
    int lo = 0, hi = S;
    while (lo < hi) { int mid = (lo + hi) >> 1; if (ids[mid] < d) lo = mid + 1; else hi = mid; }
    segs[i] = lo;
    lo = 0; hi = S;
    while (lo < hi) { int mid = (lo + hi) >> 1; if (ids[mid] <= d) lo = mid + 1; else hi = mid; }
    sege[i] = lo;
}

// ---------------- TF32 tensor-core GEMM ----------------
// C[M,N] = A[M,K] @ W[N,K]^T + epilogue. epi: 0=+bias, 1=+bias+gelu, 2=+bias+res
// fp32 bits are fed to mma.tf32 directly (HW truncates the low 13 mantissa
// bits) -- no cvt in the inner loop.
#define BM 128
#define BN 64
#define BK 16
#define BKP 20   // padded smem pitch (floats): conflict-free fragment loads

__device__ __forceinline__ void mma_tf32(float* c, const uint32_t* a, const uint32_t* b) {
    asm volatile(
        "mma.sync.aligned.m16n8k8.row.col.f32.tf32.tf32.f32 "
        "{%0,%1,%2,%3}, {%4,%5,%6,%7}, {%8,%9}, {%0,%1,%2,%3};"
        : "+f"(c[0]), "+f"(c[1]), "+f"(c[2]), "+f"(c[3])
        : "r"(a[0]), "r"(a[1]), "r"(a[2]), "r"(a[3]), "r"(b[0]), "r"(b[1]));
}

__device__ __forceinline__ void cp16(void* dst, const void* src, bool valid) {
    uint32_t d = (uint32_t)__cvta_generic_to_shared(dst);
    int sz = valid ? 16 : 0;
    asm volatile("cp.async.cg.shared.global [%0], [%1], 16, %2;\n"
                 :: "r"(d), "l"(src), "r"(sz));
}

__global__ __launch_bounds__(256) void gemm_tf32(const float* __restrict__ A,
                                                 const float* __restrict__ W,
                                                 const float* __restrict__ bias,
                                                 const float* __restrict__ res,
                                                 float* __restrict__ C,
                                                 int M, int N, int K, int epi) {
    __shared__ uint32_t As[2][BM][BKP];
    __shared__ uint32_t Ws[2][BN][BKP];

    int tid = threadIdx.x;
    int lane = tid & 31, warp = tid >> 5;
    int wm = warp & 3;        // 4 warps along M -> 32 rows each
    int wn = warp >> 2;       // 2 warps along N -> 32 cols each
    int m0 = blockIdx.y * BM;
    int n0 = blockIdx.x * BN;

    int lrow = tid >> 2;          // 0..63
    int lch = (tid & 3) * 4;      // float offset {0,4,8,12}

    float acc[2][4][4];
#pragma unroll
    for (int i = 0; i < 2; ++i)
#pragma unroll
        for (int j = 0; j < 4; ++j)
#pragma unroll
            for (int l = 0; l < 4; ++l) acc[i][j][l] = 0.f;

    int nk = K / BK;

    // prologue: stage tile 0
    {
        const float* Ab = A + (size_t)m0 * K + lch;
        cp16(&As[0][lrow][lch],      Ab + (size_t)lrow * K,        true);
        cp16(&As[0][lrow + 64][lch], Ab + (size_t)(lrow + 64) * K, true);
        cp16(&Ws[0][lrow][lch], W + (size_t)(n0 + lrow) * K + lch, (n0 + lrow) < N);
    }
    asm volatile("cp.async.commit_group;\n" ::: "memory");

    int fr = lane >> 2;   // fragment row-in-group
    int fc = lane & 3;    // fragment col-in-group

    for (int t = 0; t < nk; ++t) {
        asm volatile("cp.async.wait_group 0;\n" ::: "memory");
        __syncthreads();

        int st = t & 1;
        if (t + 1 < nk) {
            int ko = (t + 1) * BK + lch;
            const float* Ab = A + (size_t)m0 * K + ko;
            cp16(&As[st ^ 1][lrow][lch],      Ab + (size_t)lrow * K,        true);
            cp16(&As[st ^ 1][lrow + 64][lch], Ab + (size_t)(lrow + 64) * K, true);
            cp16(&Ws[st ^ 1][lrow][lch], W + (size_t)(n0 + lrow) * K + ko, (n0 + lrow) < N);
        }
        asm volatile("cp.async.commit_group;\n" ::: "memory");

#pragma unroll
        for (int kk = 0; kk < 2; ++kk) {
            int kb = kk * 8;
            uint32_t a[2][4], b[4][2];
#pragma unroll
            for (int mt = 0; mt < 2; ++mt) {
                int mr = wm * 32 + mt * 16;
                a[mt][0] = As[st][mr + fr][kb + fc];
                a[mt][1] = As[st][mr + fr + 8][kb + fc];
                a[mt][2] = As[st][mr + fr][kb + fc + 4];
                a[mt][3] = As[st][mr + fr + 8][kb + fc + 4];
            }
#pragma unroll
            for (int nt = 0; nt < 4; ++nt) {
                int nr = wn * 32 + nt * 8;
                b[nt][0] = Ws[st][nr + fr][kb + fc];
                b[nt][1] = Ws[st][nr + fr][kb + fc + 4];
            }
#pragma unroll
            for (int mt = 0; mt < 2; ++mt)
#pragma unroll
                for (int nt = 0; nt < 4; ++nt)
                    mma_tf32(acc[mt][nt], a[mt], b[nt]);
        }
    }

    // epilogue
#pragma unroll
    for (int mt = 0; mt < 2; ++mt) {
        int row = m0 + wm * 32 + mt * 16 + fr;
#pragma unroll
        for (int nt = 0; nt < 4; ++nt) {
            int col = n0 + wn * 32 + nt * 8 + fc * 2;
#pragma unroll
            for (int l = 0; l < 4; ++l) {
                int r = row + ((l >> 1) ? 8 : 0);
                int c = col + (l & 1);
                if (c >= N) continue;
                float v = acc[mt][nt][l] + bias[c];
                if (epi == 1) {
                    float u = 0.7978845608028654f * (v + 0.044715f * v * v * v);
                    float e = __expf(2.f * u);
                    float th = 1.f - 2.f / (e + 1.f);
                    v = 0.5f * v * (1.0f + th);
                } else if (epi == 2) {
                    v += res[(size_t)r * N + c];
                }
                C[(size_t)r * N + c] = v;
            }
        }
    }
}

// ---------------- tiled document-masked attention ----------------
// block = 256 threads, grid (S/64, NH). Each block: 64 queries x 1 head.
// Warp w owns query rows w*8..w*8+7. K/V chunks of 64 in smem (pitch 73).
#define QT 64
#define KT 64
#define KP 73
#define PP 65

__global__ __launch_bounds__(256) void attn_tile(const float* __restrict__ Q,
                                                 const float* __restrict__ Km,
                                                 const float* __restrict__ V,
                                                 const int* __restrict__ segs,
                                                 const int* __restrict__ sege,
                                                 float* __restrict__ O) {
    extern __shared__ float sm[];
    float* Qs = sm;                 // QT*KP
    float* Ks = Qs + QT * KP;       // KT*KP
    float* Vs = Ks + KT * KP;       // KT*KP
    float* Ps = Vs + KT * KP;       // QT*PP

    int h = blockIdx.y;
    int q0 = blockIdx.x * QT;
    int tid = threadIdx.x, lane = tid & 31, warp = tid >> 5;
    const float scale = 0.11785113019775793f;   // 72^-0.5

    // stage Q tile
    for (int idx = tid; idx < QT * HD; idx += 256) {
        int r = idx / HD, d = idx - r * HD;
        Qs[r * KP + d] = Q[(size_t)(q0 + r) * H + h * HD + d];
    }

    int s0[8], s1[8];
    float mrow[8], lrow[8], o[8][3];
#pragma unroll
    for (int i = 0; i < 8; ++i) {
        int qg = q0 + warp * 8 + i;
        s0[i] = segs[qg];
        s1[i] = sege[qg];
        mrow[i] = -3.0e38f;
        lrow[i] = 0.f;
        o[i][0] = o[i][1] = o[i][2] = 0.f;
    }

    int kstart = segs[q0];
    int kend = sege[q0 + QT - 1];
    int d2ok = (lane + 64 < HD);

    for (int c0 = kstart; c0 < kend; c0 += KT) {
        int len = min(KT, kend - c0);
        __syncthreads();   // previous chunk fully consumed
        for (int idx = tid; idx < KT * HD; idx += 256) {
            int r = idx / HD, d = idx - r * HD;
            float kv = 0.f, vv = 0.f;
            if (r < len) {
                size_t g = (size_t)(c0 + r) * H + h * HD + d;
                kv = Km[g];
                vv = V[g];
            }
            Ks[r * KP + d] = kv;
            Vs[r * KP + d] = vv;
        }
        __syncthreads();

        // scores: lane covers keys {lane, lane+32} for 8 q rows
        float sc[8][2];
#pragma unroll
        for (int i = 0; i < 8; ++i) { sc[i][0] = 0.f; sc[i][1] = 0.f; }
        const float* qb = Qs + (warp * 8) * KP;
        for (int d = 0; d < HD; ++d) {
            float k0v = Ks[lane * KP + d];
            float k1v = Ks[(lane + 32) * KP + d];
#pragma unroll
            for (int i = 0; i < 8; ++i) {
                float qd = qb[i * KP + d];
                sc[i][0] = fmaf(qd, k0v, sc[i][0]);
                sc[i][1] = fmaf(qd, k1v, sc[i][1]);
            }
        }

        int kg0 = c0 + lane, kg1 = c0 + lane + 32;
#pragma unroll
        for (int i = 0; i < 8; ++i) {
            bool v0ok = (kg0 >= s0[i]) && (kg0 < s1[i]);
            bool v1ok = (kg1 >= s0[i]) && (kg1 < s1[i]);
            float v0 = v0ok ? sc[i][0] * scale : -3.0e38f;
            float v1 = v1ok ? sc[i][1] * scale : -3.0e38f;
            float mx = fmaxf(v0, v1);
#pragma unroll
            for (int ofs = 16; ofs > 0; ofs >>= 1)
                mx = fmaxf(mx, __shfl_xor_sync(0xffffffffu, mx, ofs));
            float mnew = fmaxf(mrow[i], mx);
            float p0 = v0ok ? __expf(v0 - mnew) : 0.f;
            float p1 = v1ok ? __expf(v1 - mnew) : 0.f;
            float ps = p0 + p1;
#pragma unroll
            for (int ofs = 16; ofs > 0; ofs >>= 1)
                ps += __shfl_xor_sync(0xffffffffu, ps, ofs);
            float corr = __expf(mrow[i] - mnew);
            lrow[i] = lrow[i] * corr + ps;
            mrow[i] = mnew;
            o[i][0] *= corr; o[i][1] *= corr; o[i][2] *= corr;
            Ps[(warp * 8 + i) * PP + lane] = p0;
            Ps[(warp * 8 + i) * PP + lane + 32] = p1;
        }
        __syncwarp();

        // V accumulation: lane owns dims {lane, lane+32, lane+64}
        for (int k = 0; k < len; ++k) {
            float vv0 = Vs[k * KP + lane];
            float vv1 = Vs[k * KP + lane + 32];
            float vv2 = d2ok ? Vs[k * KP + lane + 64] : 0.f;
#pragma unroll
            for (int i = 0; i < 8; ++i) {
                float p = Ps[(warp * 8 + i) * PP + k];
                o[i][0] = fmaf(p, vv0, o[i][0]);
                o[i][1] = fmaf(p, vv1, o[i][1]);
                o[i][2] = fmaf(p, vv2, o[i][2]);
            }
        }
    }

#pragma unroll
    for (int i = 0; i < 8; ++i) {
        float inv = 1.f / lrow[i];
        size_t base = (size_t)(q0 + warp * 8 + i) * H + h * HD;
        O[base + lane] = o[i][0] * inv;
        O[base + lane + 32] = o[i][1] * inv;
        if (d2ok) O[base + lane + 64] = o[i][2] * inv;
    }
}

// ---------------- launch ----------------
extern "C" void kernel_launch(void* const* d_in, const int* in_sizes, int n_in,
                              void* d_out, int out_size) {
    const float* hs    = (const float*)d_in[0];
    const int*   doc   = (const int*)d_in[1];
    const float* q_w   = (const float*)d_in[2];
    const float* q_b   = (const float*)d_in[3];
    const float* k_w   = (const float*)d_in[4];
    const float* k_b   = (const float*)d_in[5];
    const float* v_w   = (const float*)d_in[6];
    const float* v_b   = (const float*)d_in[7];
    const float* o_w   = (const float*)d_in[8];
    const float* o_b   = (const float*)d_in[9];
    const float* ln1_g = (const float*)d_in[10];
    const float* ln1_b = (const float*)d_in[11];
    const float* ln2_g = (const float*)d_in[12];
    const float* ln2_b = (const float*)d_in[13];
    const float* fc1_w = (const float*)d_in[14];
    const float* fc1_b = (const float*)d_in[15];
    const float* fc2_w = (const float*)d_in[16];
    const float* fc2_b = (const float*)d_in[17];
    float* out = (float*)d_out;

    float *xn, *q, *k, *v, *attn, *hid, *y, *ff;
    int *segs, *sege;
    cudaGetSymbolAddress((void**)&xn,   g_xn);
    cudaGetSymbolAddress((void**)&q,    g_q);
    cudaGetSymbolAddress((void**)&k,    g_k);
    cudaGetSymbolAddress((void**)&v,    g_v);
    cudaGetSymbolAddress((void**)&attn, g_attn);
    cudaGetSymbolAddress((void**)&hid,  g_hid);
    cudaGetSymbolAddress((void**)&y,    g_y);
    cudaGetSymbolAddress((void**)&ff,   g_ff);
    cudaGetSymbolAddress((void**)&segs, g_segs);
    cudaGetSymbolAddress((void**)&sege, g_sege);

    int att_smem = (QT * KP + 2 * KT * KP + QT * PP) * (int)sizeof(float);
    static bool attr_set = false;
    if (!attr_set) {
        cudaFuncSetAttribute(attn_tile, cudaFuncAttributeMaxDynamicSharedMemorySize, att_smem);
        attr_set = true;
    }

    dim3 gH(H / BN, S / BM);                 // (18, 32)
    dim3 gF((FF + BN - 1) / BN, S / BM);     // (68, 32)

    ln_kernel<<<S, 256>>>(hs, ln1_g, ln1_b, xn);
    doc_ranges<<<(S + 255) / 256, 256>>>(doc, segs, sege);

    gemm_tf32<<<gH, 256>>>(xn, q_w, q_b, nullptr, q, S, H, H, 0);
    gemm_tf32<<<gH, 256>>>(xn, k_w, k_b, nullptr, k, S, H, H, 0);
    gemm_tf32<<<gH, 256>>>(xn, v_w, v_b, nullptr, v, S, H, H, 0);

    attn_tile<<<dim3(S / QT, NH), 256, att_smem>>>(q, k, v, segs, sege, attn);

    gemm_tf32<<<gH, 256>>>(attn, o_w, o_b, hs, hid, S, H, H, 2);

    ln_kernel<<<S, 256>>>(hid, ln2_g, ln2_b, y);

    gemm_tf32<<<gF, 256>>>(y, fc1_w, fc1_b, nullptr, ff, S, FF, H, 1);
    gemm_tf32<<<gH, 256>>>(ff, fc2_w, fc2_b, hid, out, S, H, FF, 2);
}

// round 4
// speedup vs baseline: 4.9910x; 1.2076x over previous
#include <cuda_runtime.h>
#include <math.h>
#include <stdint.h>

#define S 4096
#define H 1152
#define NH 16
#define HD 72
#define FF 4304
#define LN_EPS 1e-6f

// ---------------- scratch (allocation-free: device globals) ----------------
__device__ float g_xn[S * H];
__device__ float g_q[S * H];
__device__ float g_k[S * H];
__device__ float g_v[S * H];
__device__ float g_attn[S * H];
__device__ float g_hid[S * H];
__device__ float g_y[S * H];
__device__ float g_ff[(size_t)S * FF];
__device__ int g_segs[S];
__device__ int g_sege[S];

// ---------------- LayerNorm: one block per row ----------------
__global__ __launch_bounds__(256) void ln_kernel(const float* __restrict__ x,
                                                 const float* __restrict__ g,
                                                 const float* __restrict__ b,
                                                 float* __restrict__ y) {
    int row = blockIdx.x;
    const float* xr = x + (size_t)row * H;
    __shared__ float red[256];
    int tid = threadIdx.x;

    float s = 0.f;
    for (int i = tid; i < H; i += 256) s += xr[i];
    red[tid] = s;
    __syncthreads();
    for (int off = 128; off > 0; off >>= 1) {
        if (tid < off) red[tid] += red[tid + off];
        __syncthreads();
    }
    float mu = red[0] * (1.0f / H);
    __syncthreads();

    float sq = 0.f;
    for (int i = tid; i < H; i += 256) {
        float d = xr[i] - mu;
        sq += d * d;
    }
    red[tid] = sq;
    __syncthreads();
    for (int off = 128; off > 0; off >>= 1) {
        if (tid < off) red[tid] += red[tid + off];
        __syncthreads();
    }
    float inv = rsqrtf(red[0] * (1.0f / H) + LN_EPS);

    float* yr = y + (size_t)row * H;
    for (int i = tid; i < H; i += 256)
        yr[i] = (xr[i] - mu) * inv * g[i] + b[i];
}

// ---------------- document segment ranges (ids are sorted) ----------------
__global__ void doc_ranges(const int* __restrict__ ids, int* __restrict__ segs,
                           int* __restrict__ sege) {
    int i = blockIdx.x * blockDim.x + threadIdx.x;
    if (i >= S) return;
    int d = ids[i];
    int lo = 0, hi = S;
    while (lo < hi) { int mid = (lo + hi) >> 1; if (ids[mid] < d) lo = mid + 1; else hi = mid; }
    segs[i] = lo;
    lo = 0; hi = S;
    while (lo < hi) { int mid = (lo + hi) >> 1; if (ids[mid] <= d) lo = mid + 1; else hi = mid; }
    sege[i] = lo;
}

// ---------------- TF32 tensor-core GEMM ----------------
// C[M,N] = A[M,K] @ W[N,K]^T + epilogue. epi: 0=+bias, 1=+bias+gelu, 2=+bias+res
// 128x128 block tile, warp tile 64x32 (2 warps M x 4 warps N), double-buffered
// cp.async. fp32 bits fed straight to mma.tf32 (HW truncates mantissa).
#define BM 128
#define BN 128
#define BK 16
#define BKP 20   // padded smem pitch (floats): conflict-free fragment loads

__device__ __forceinline__ void mma_tf32(float* c, const uint32_t* a, const uint32_t* b) {
    asm volatile(
        "mma.sync.aligned.m16n8k8.row.col.f32.tf32.tf32.f32 "
        "{%0,%1,%2,%3}, {%4,%5,%6,%7}, {%8,%9}, {%0,%1,%2,%3};"
        : "+f"(c[0]), "+f"(c[1]), "+f"(c[2]), "+f"(c[3])
        : "r"(a[0]), "r"(a[1]), "r"(a[2]), "r"(a[3]), "r"(b[0]), "r"(b[1]));
}

__device__ __forceinline__ void cp16(void* dst, const void* src, bool valid) {
    uint32_t d = (uint32_t)__cvta_generic_to_shared(dst);
    int sz = valid ? 16 : 0;
    asm volatile("cp.async.cg.shared.global [%0], [%1], 16, %2;\n"
                 :: "r"(d), "l"(src), "r"(sz));
}

__global__ __launch_bounds__(256, 2) void gemm_tf32(const float* __restrict__ A,
                                                    const float* __restrict__ W,
                                                    const float* __restrict__ bias,
                                                    const float* __restrict__ res,
                                                    float* __restrict__ C,
                                                    int M, int N, int K, int epi) {
    __shared__ uint32_t As[2][BM][BKP];
    __shared__ uint32_t Ws[2][BN][BKP];

    int tid = threadIdx.x;
    int lane = tid & 31, warp = tid >> 5;
    int wn = warp & 3;        // 4 warps along N -> 32 cols each
    int wm = warp >> 2;       // 2 warps along M -> 64 rows each
    int m0 = blockIdx.y * BM;
    int n0 = blockIdx.x * BN;

    int lrow = tid >> 2;          // 0..63
    int lch = (tid & 3) * 4;      // float offset {0,4,8,12}

    float acc[4][4][4];
#pragma unroll
    for (int i = 0; i < 4; ++i)
#pragma unroll
        for (int j = 0; j < 4; ++j)
#pragma unroll
            for (int l = 0; l < 4; ++l) acc[i][j][l] = 0.f;

    int nk = K / BK;

    // prologue: stage tile 0
    {
        const float* Ab = A + (size_t)m0 * K + lch;
        cp16(&As[0][lrow][lch],      Ab + (size_t)lrow * K,        true);
        cp16(&As[0][lrow + 64][lch], Ab + (size_t)(lrow + 64) * K, true);
        cp16(&Ws[0][lrow][lch],      W + (size_t)(n0 + lrow) * K + lch,      (n0 + lrow) < N);
        cp16(&Ws[0][lrow + 64][lch], W + (size_t)(n0 + lrow + 64) * K + lch, (n0 + lrow + 64) < N);
    }
    asm volatile("cp.async.commit_group;\n" ::: "memory");

    int fr = lane >> 2;   // fragment row-in-group
    int fc = lane & 3;    // fragment col-in-group

    for (int t = 0; t < nk; ++t) {
        asm volatile("cp.async.wait_group 0;\n" ::: "memory");
        __syncthreads();

        int st = t & 1;
        if (t + 1 < nk) {
            int ko = (t + 1) * BK + lch;
            const float* Ab = A + (size_t)m0 * K + ko;
            cp16(&As[st ^ 1][lrow][lch],      Ab + (size_t)lrow * K,        true);
            cp16(&As[st ^ 1][lrow + 64][lch], Ab + (size_t)(lrow + 64) * K, true);
            cp16(&Ws[st ^ 1][lrow][lch],      W + (size_t)(n0 + lrow) * K + ko,      (n0 + lrow) < N);
            cp16(&Ws[st ^ 1][lrow + 64][lch], W + (size_t)(n0 + lrow + 64) * K + ko, (n0 + lrow + 64) < N);
        }
        asm volatile("cp.async.commit_group;\n" ::: "memory");

#pragma unroll
        for (int kk = 0; kk < 2; ++kk) {
            int kb = kk * 8;
            uint32_t a[4][4], b[4][2];
#pragma unroll
            for (int mt = 0; mt < 4; ++mt) {
                int mr = wm * 64 + mt * 16;
                a[mt][0] = As[st][mr + fr][kb + fc];
                a[mt][1] = As[st][mr + fr + 8][kb + fc];
                a[mt][2] = As[st][mr + fr][kb + fc + 4];
                a[mt][3] = As[st][mr + fr + 8][kb + fc + 4];
            }
#pragma unroll
            for (int nt = 0; nt < 4; ++nt) {
                int nr = wn * 32 + nt * 8;
                b[nt][0] = Ws[st][nr + fr][kb + fc];
                b[nt][1] = Ws[st][nr + fr][kb + fc + 4];
            }
#pragma unroll
            for (int mt = 0; mt < 4; ++mt)
#pragma unroll
                for (int nt = 0; nt < 4; ++nt)
                    mma_tf32(acc[mt][nt], a[mt], b[nt]);
        }
    }

    // epilogue
#pragma unroll
    for (int mt = 0; mt < 4; ++mt) {
        int row = m0 + wm * 64 + mt * 16 + fr;
#pragma unroll
        for (int nt = 0; nt < 4; ++nt) {
            int col = n0 + wn * 32 + nt * 8 + fc * 2;
#pragma unroll
            for (int l = 0; l < 4; ++l) {
                int r = row + ((l >> 1) ? 8 : 0);
                int c = col + (l & 1);
                if (c >= N) continue;
                float v = acc[mt][nt][l] + bias[c];
                if (epi == 1) {
                    float u = 0.7978845608028654f * (v + 0.044715f * v * v * v);
                    float e = __expf(2.f * u);
                    float th = 1.f - 2.f / (e + 1.f);
                    v = 0.5f * v * (1.0f + th);
                } else if (epi == 2) {
                    v += res[(size_t)r * N + c];
                }
                C[(size_t)r * N + c] = v;
            }
        }
    }
}

// ---------------- tiled document-masked attention ----------------
// block = 256 threads, grid (S/64, NH). Each block: 64 queries x 1 head.
// Warp w owns query rows w*8..w*8+7. K/V chunks of 64 in smem (pitch 73).
#define QT 64
#define KT 64
#define KP 73
#define PP 65

__global__ __launch_bounds__(256) void attn_tile(const float* __restrict__ Q,
                                                 const float* __restrict__ Km,
                                                 const float* __restrict__ V,
                                                 const int* __restrict__ segs,
                                                 const int* __restrict__ sege,
                                                 float* __restrict__ O) {
    extern __shared__ float sm[];
    float* Qs = sm;                 // QT*KP
    float* Ks = Qs + QT * KP;       // KT*KP
    float* Vs = Ks + KT * KP;       // KT*KP
    float* Ps = Vs + KT * KP;       // QT*PP

    int h = blockIdx.y;
    int q0 = blockIdx.x * QT;
    int tid = threadIdx.x, lane = tid & 31, warp = tid >> 5;
    const float scale = 0.11785113019775793f;   // 72^-0.5

    // stage Q tile
    for (int idx = tid; idx < QT * HD; idx += 256) {
        int r = idx / HD, d = idx - r * HD;
        Qs[r * KP + d] = Q[(size_t)(q0 + r) * H + h * HD + d];
    }

    int s0[8], s1[8];
    float mrow[8], lrow[8], o[8][3];
#pragma unroll
    for (int i = 0; i < 8; ++i) {
        int qg = q0 + warp * 8 + i;
        s0[i] = segs[qg];
        s1[i] = sege[qg];
        mrow[i] = -3.0e38f;
        lrow[i] = 0.f;
        o[i][0] = o[i][1] = o[i][2] = 0.f;
    }

    int kstart = segs[q0];
    int kend = sege[q0 + QT - 1];
    int d2ok = (lane + 64 < HD);

    for (int c0 = kstart; c0 < kend; c0 += KT) {
        int len = min(KT, kend - c0);
        __syncthreads();   // previous chunk fully consumed
        for (int idx = tid; idx < KT * HD; idx += 256) {
            int r = idx / HD, d = idx - r * HD;
            float kv = 0.f, vv = 0.f;
            if (r < len) {
                size_t g = (size_t)(c0 + r) * H + h * HD + d;
                kv = Km[g];
                vv = V[g];
            }
            Ks[r * KP + d] = kv;
            Vs[r * KP + d] = vv;
        }
        __syncthreads();

        // scores: lane covers keys {lane, lane+32} for 8 q rows
        float sc[8][2];
#pragma unroll
        for (int i = 0; i < 8; ++i) { sc[i][0] = 0.f; sc[i][1] = 0.f; }
        const float* qb = Qs + (warp * 8) * KP;
        for (int d = 0; d < HD; ++d) {
            float k0v = Ks[lane * KP + d];
            float k1v = Ks[(lane + 32) * KP + d];
#pragma unroll
            for (int i = 0; i < 8; ++i) {
                float qd = qb[i * KP + d];
                sc[i][0] = fmaf(qd, k0v, sc[i][0]);
                sc[i][1] = fmaf(qd, k1v, sc[i][1]);
            }
        }

        int kg0 = c0 + lane, kg1 = c0 + lane + 32;
#pragma unroll
        for (int i = 0; i < 8; ++i) {
            bool v0ok = (kg0 >= s0[i]) && (kg0 < s1[i]);
            bool v1ok = (kg1 >= s0[i]) && (kg1 < s1[i]);
            float v0 = v0ok ? sc[i][0] * scale : -3.0e38f;
            float v1 = v1ok ? sc[i][1] * scale : -3.0e38f;
            float mx = fmaxf(v0, v1);
#pragma unroll
            for (int ofs = 16; ofs > 0; ofs >>= 1)
                mx = fmaxf(mx, __shfl_xor_sync(0xffffffffu, mx, ofs));
            float mnew = fmaxf(mrow[i], mx);
            float p0 = v0ok ? __expf(v0 - mnew) : 0.f;
            float p1 = v1ok ? __expf(v1 - mnew) : 0.f;
            float ps = p0 + p1;
#pragma unroll
            for (int ofs = 16; ofs > 0; ofs >>= 1)
                ps += __shfl_xor_sync(0xffffffffu, ps, ofs);
            float corr = __expf(mrow[i] - mnew);
            lrow[i] = lrow[i] * corr + ps;
            mrow[i] = mnew;
            o[i][0] *= corr; o[i][1] *= corr; o[i][2] *= corr;
            Ps[(warp * 8 + i) * PP + lane] = p0;
            Ps[(warp * 8 + i) * PP + lane + 32] = p1;
        }
        __syncwarp();

        // V accumulation: lane owns dims {lane, lane+32, lane+64}
        for (int k = 0; k < len; ++k) {
            float vv0 = Vs[k * KP + lane];
            float vv1 = Vs[k * KP + lane + 32];
            float vv2 = d2ok ? Vs[k * KP + lane + 64] : 0.f;
#pragma unroll
            for (int i = 0; i < 8; ++i) {
                float p = Ps[(warp * 8 + i) * PP + k];
                o[i][0] = fmaf(p, vv0, o[i][0]);
                o[i][1] = fmaf(p, vv1, o[i][1]);
                o[i][2] = fmaf(p, vv2, o[i][2]);
            }
        }
    }

#pragma unroll
    for (int i = 0; i < 8; ++i) {
        float inv = 1.f / lrow[i];
        size_t base = (size_t)(q0 + warp * 8 + i) * H + h * HD;
        O[base + lane] = o[i][0] * inv;
        O[base + lane + 32] = o[i][1] * inv;
        if (d2ok) O[base + lane + 64] = o[i][2] * inv;
    }
}

// ---------------- launch ----------------
extern "C" void kernel_launch(void* const* d_in, const int* in_sizes, int n_in,
                              void* d_out, int out_size) {
    const float* hs    = (const float*)d_in[0];
    const int*   doc   = (const int*)d_in[1];
    const float* q_w   = (const float*)d_in[2];
    const float* q_b   = (const float*)d_in[3];
    const float* k_w   = (const float*)d_in[4];
    const float* k_b   = (const float*)d_in[5];
    const float* v_w   = (const float*)d_in[6];
    const float* v_b   = (const float*)d_in[7];
    const float* o_w   = (const float*)d_in[8];
    const float* o_b   = (const float*)d_in[9];
    const float* ln1_g = (const float*)d_in[10];
    const float* ln1_b = (const float*)d_in[11];
    const float* ln2_g = (const float*)d_in[12];
    const float* ln2_b = (const float*)d_in[13];
    const float* fc1_w = (const float*)d_in[14];
    const float* fc1_b = (const float*)d_in[15];
    const float* fc2_w = (const float*)d_in[16];
    const float* fc2_b = (const float*)d_in[17];
    float* out = (float*)d_out;

    float *xn, *q, *k, *v, *attn, *hid, *y, *ff;
    int *segs, *sege;
    cudaGetSymbolAddress((void**)&xn,   g_xn);
    cudaGetSymbolAddress((void**)&q,    g_q);
    cudaGetSymbolAddress((void**)&k,    g_k);
    cudaGetSymbolAddress((void**)&v,    g_v);
    cudaGetSymbolAddress((void**)&attn, g_attn);
    cudaGetSymbolAddress((void**)&hid,  g_hid);
    cudaGetSymbolAddress((void**)&y,    g_y);
    cudaGetSymbolAddress((void**)&ff,   g_ff);
    cudaGetSymbolAddress((void**)&segs, g_segs);
    cudaGetSymbolAddress((void**)&sege, g_sege);

    int att_smem = (QT * KP + 2 * KT * KP + QT * PP) * (int)sizeof(float);
    static bool attr_set = false;
    if (!attr_set) {
        cudaFuncSetAttribute(attn_tile, cudaFuncAttributeMaxDynamicSharedMemorySize, att_smem);
        attr_set = true;
    }

    dim3 gH(H / BN, S / BM);                 // (9, 32)
    dim3 gF((FF + BN - 1) / BN, S / BM);     // (34, 32)

    ln_kernel<<<S, 256>>>(hs, ln1_g, ln1_b, xn);
    doc_ranges<<<(S + 255) / 256, 256>>>(doc, segs, sege);

    gemm_tf32<<<gH, 256>>>(xn, q_w, q_b, nullptr, q, S, H, H, 0);
    gemm_tf32<<<gH, 256>>>(xn, k_w, k_b, nullptr, k, S, H, H, 0);
    gemm_tf32<<<gH, 256>>>(xn, v_w, v_b, nullptr, v, S, H, H, 0);

    attn_tile<<<dim3(S / QT, NH), 256, att_smem>>>(q, k, v, segs, sege, attn);

    gemm_tf32<<<gH, 256>>>(attn, o_w, o_b, hs, hid, S, H, H, 2);

    ln_kernel<<<S, 256>>>(hid, ln2_g, ln2_b, y);

    gemm_tf32<<<gF, 256>>>(y, fc1_w, fc1_b, nullptr, ff, S, FF, H, 1);
    gemm_tf32<<<gH, 256>>>(ff, fc2_w, fc2_b, hid, out, S, H, FF, 2);
}

// round 9
// speedup vs baseline: 6.8692x; 1.3763x over previous
#include <cuda_runtime.h>
#include <cuda_fp16.h>
#include <math.h>
#include <stdint.h>

#define S 4096
#define H 1152
#define NH 16
#define HD 72
#define FF 4304
#define LN_EPS 1e-6f

// ---------------- scratch (allocation-free: device globals) ----------------
__device__ __half g_xnh[S * H];
__device__ float  g_q[S * H];
__device__ float  g_k[S * H];
__device__ float  g_v[S * H];
__device__ __half g_attnh[S * H];
__device__ float  g_hid[S * H];
__device__ __half g_yh[S * H];
__device__ __half g_ffh[(size_t)S * FF];
__device__ __half g_qwh[H * H];
__device__ __half g_kwh[H * H];
__device__ __half g_vwh[H * H];
__device__ __half g_owh[H * H];
__device__ __half g_fc1h[(size_t)H * FF];
__device__ __half g_fc2h[(size_t)H * FF];
__device__ int g_segs[S];
__device__ int g_sege[S];

// ---------------- weight conversion: float -> half ----------------
__global__ __launch_bounds__(256) void cvt_f2h(const float4* __restrict__ x,
                                               __half2* __restrict__ y, int n4) {
    int i = blockIdx.x * blockDim.x + threadIdx.x;
    if (i < n4) {
        float4 v = x[i];
        y[2 * i]     = __floats2half2_rn(v.x, v.y);
        y[2 * i + 1] = __floats2half2_rn(v.z, v.w);
    }
}

// ---------------- LayerNorm: one block per row, half output ----------------
__global__ __launch_bounds__(256) void ln_kernel_h(const float* __restrict__ x,
                                                   const float* __restrict__ g,
                                                   const float* __restrict__ b,
                                                   __half* __restrict__ y) {
    int row = blockIdx.x;
    const float* xr = x + (size_t)row * H;
    __shared__ float red[256];
    int tid = threadIdx.x;

    float s = 0.f;
    for (int i = tid; i < H; i += 256) s += xr[i];
    red[tid] = s;
    __syncthreads();
    for (int off = 128; off > 0; off >>= 1) {
        if (tid < off) red[tid] += red[tid + off];
        __syncthreads();
    }
    float mu = red[0] * (1.0f / H);
    __syncthreads();

    float sq = 0.f;
    for (int i = tid; i < H; i += 256) {
        float d = xr[i] - mu;
        sq += d * d;
    }
    red[tid] = sq;
    __syncthreads();
    for (int off = 128; off > 0; off >>= 1) {
        if (tid < off) red[tid] += red[tid + off];
        __syncthreads();
    }
    float inv = rsqrtf(red[0] * (1.0f / H) + LN_EPS);

    __half* yr = y + (size_t)row * H;
    for (int i = tid; i < H; i += 256)
        yr[i] = __float2half((xr[i] - mu) * inv * g[i] + b[i]);
}

// ---------------- document segment ranges (ids are sorted) ----------------
__global__ void doc_ranges(const int* __restrict__ ids, int* __restrict__ segs,
                           int* __restrict__ sege) {
    int i = blockIdx.x * blockDim.x + threadIdx.x;
    if (i >= S) return;
    int d = ids[i];
    int lo = 0, hi = S;
    while (lo < hi) { int mid = (lo + hi) >> 1; if (ids[mid] < d) lo = mid + 1; else hi = mid; }
    segs[i] = lo;
    lo = 0; hi = S;
    while (lo < hi) { int mid = (lo + hi) >> 1; if (ids[mid] <= d) lo = mid + 1; else hi = mid; }
    sege[i] = lo;
}

// ---------------- FP16 tensor-core GEMM (m16n8k16, fp32 accum) -------------
// C[M,N] = A[M,K] @ W[N,K]^T + epilogue. epi: 0=+bias, 1=+bias+gelu, 2=+bias+res
// 128x128 tile, warp tile 64x32, BK=32 halves, double-buffered cp.async,
// padded pitch-40 smem. Guarded cp.async sources are CLAMPED in-bounds
// (never carry an OOB address, even with src-size=0).
#define BM 128
#define BN 128
#define BKH 32
#define PITCH 40

__device__ __forceinline__ void mma_f16(float* c, const uint32_t* a, const uint32_t* b) {
    asm volatile(
        "mma.sync.aligned.m16n8k16.row.col.f32.f16.f16.f32 "
        "{%0,%1,%2,%3}, {%4,%5,%6,%7}, {%8,%9}, {%0,%1,%2,%3};"
        : "+f"(c[0]), "+f"(c[1]), "+f"(c[2]), "+f"(c[3])
        : "r"(a[0]), "r"(a[1]), "r"(a[2]), "r"(a[3]), "r"(b[0]), "r"(b[1]));
}

__device__ __forceinline__ void cp16(void* dst, const void* src, bool valid,
                                     const void* safe) {
    uint32_t d = (uint32_t)__cvta_generic_to_shared(dst);
    const void* s = valid ? src : safe;   // in-bounds address even when ZFILLing
    int sz = valid ? 16 : 0;
    asm volatile("cp.async.cg.shared.global [%0], [%1], 16, %2;\n"
                 :: "r"(d), "l"(s), "r"(sz));
}

__global__ __launch_bounds__(256, 2) void gemm_f16(const __half* __restrict__ A,
                                                   const __half* __restrict__ W,
                                                   const float* __restrict__ bias,
                                                   const float* __restrict__ res,
                                                   float* __restrict__ C,
                                                   __half* __restrict__ Ch,
                                                   int M, int N, int K, int epi) {
    __shared__ __half As[2][BM][PITCH];
    __shared__ __half Ws[2][BN][PITCH];

    int tid = threadIdx.x;
    int lane = tid & 31, warp = tid >> 5;
    int wn = warp & 3;        // 4 warps along N -> 32 cols each
    int wm = warp >> 2;       // 2 warps along M -> 64 rows each
    int m0 = blockIdx.y * BM;
    int n0 = blockIdx.x * BN;

    // staging decomposition: each thread covers one row-half (2 x 16B chunks)
    int lr = tid >> 1;             // 0..127  tile row
    int lc = (tid & 1) * 2;        // chunk pair {0,1} or {2,3}

    const __half* Ab = A + (size_t)m0 * K;

    float acc[4][4][4];
#pragma unroll
    for (int i = 0; i < 4; ++i)
#pragma unroll
        for (int j = 0; j < 4; ++j)
#pragma unroll
            for (int l = 0; l < 4; ++l) acc[i][j][l] = 0.f;

    int nk = (K + BKH - 1) / BKH;

    // prologue: stage tile 0 into buffer 0
    {
#pragma unroll
        for (int cc = 0; cc < 2; ++cc) {
            int c = lc + cc;
            cp16(&As[0][lr][c * 8], Ab + (size_t)lr * K + c * 8,
                 (c * 8 + 8 <= K), A);
            cp16(&Ws[0][lr][c * 8], W + (size_t)(n0 + lr) * K + c * 8,
                 ((n0 + lr) < N) && (c * 8 + 8 <= K), W);
        }
    }
    asm volatile("cp.async.commit_group;\n" ::: "memory");

    int fr = lane >> 2;   // 0..7
    int fc = lane & 3;    // 0..3

    for (int t = 0; t < nk; ++t) {
        asm volatile("cp.async.wait_group 0;\n" ::: "memory");
        __syncthreads();

        int st = t & 1;
        if (t + 1 < nk) {
            int ko = (t + 1) * BKH;
#pragma unroll
            for (int cc = 0; cc < 2; ++cc) {
                int c = lc + cc;
                cp16(&As[st ^ 1][lr][c * 8], Ab + (size_t)lr * K + ko + c * 8,
                     (ko + c * 8 + 8 <= K), A);
                cp16(&Ws[st ^ 1][lr][c * 8], W + (size_t)(n0 + lr) * K + ko + c * 8,
                     ((n0 + lr) < N) && (ko + c * 8 + 8 <= K), W);
            }
        }
        asm volatile("cp.async.commit_group;\n" ::: "memory");

#pragma unroll
        for (int kk = 0; kk < 2; ++kk) {
            int kb = kk * 16;
            uint32_t a[4][4], b[4][2];
#pragma unroll
            for (int mt = 0; mt < 4; ++mt) {
                int mr = wm * 64 + mt * 16;
                a[mt][0] = *(const uint32_t*)&As[st][mr + fr][kb + fc * 2];
                a[mt][1] = *(const uint32_t*)&As[st][mr + fr + 8][kb + fc * 2];
                a[mt][2] = *(const uint32_t*)&As[st][mr + fr][kb + fc * 2 + 8];
                a[mt][3] = *(const uint32_t*)&As[st][mr + fr + 8][kb + fc * 2 + 8];
            }
#pragma unroll
            for (int nt = 0; nt < 4; ++nt) {
                int nr = wn * 32 + nt * 8;
                b[nt][0] = *(const uint32_t*)&Ws[st][nr + fr][kb + fc * 2];
                b[nt][1] = *(const uint32_t*)&Ws[st][nr + fr][kb + fc * 2 + 8];
            }
#pragma unroll
            for (int mt = 0; mt < 4; ++mt)
#pragma unroll
                for (int nt = 0; nt < 4; ++nt)
                    mma_f16(acc[mt][nt], a[mt], b[nt]);
        }
    }

    // epilogue
#pragma unroll
    for (int mt = 0; mt < 4; ++mt) {
        int row = m0 + wm * 64 + mt * 16 + fr;
#pragma unroll
        for (int nt = 0; nt < 4; ++nt) {
            int col = n0 + wn * 32 + nt * 8 + fc * 2;
#pragma unroll
            for (int l = 0; l < 4; ++l) {
                int r = row + ((l >> 1) ? 8 : 0);
                int c = col + (l & 1);
                if (c >= N) continue;
                float v = acc[mt][nt][l] + bias[c];
                if (epi == 1) {
                    float u = 0.7978845608028654f * (v + 0.044715f * v * v * v);
                    float e = __expf(2.f * u);
                    float th = 1.f - 2.f / (e + 1.f);
                    v = 0.5f * v * (1.0f + th);
                } else if (epi == 2) {
                    v += res[(size_t)r * N + c];
                }
                if (Ch) Ch[(size_t)r * N + c] = __float2half(v);
                else    C[(size_t)r * N + c] = v;
            }
        }
    }
}

// ---------------- tiled document-masked attention (half output) ------------
#define QT 64
#define KT 64
#define KP 73
#define PP 65

__global__ __launch_bounds__(256) void attn_tile(const float* __restrict__ Q,
                                                 const float* __restrict__ Km,
                                                 const float* __restrict__ V,
                                                 const int* __restrict__ segs,
                                                 const int* __restrict__ sege,
                                                 __half* __restrict__ O) {
    extern __shared__ float sm[];
    float* Qs = sm;                 // QT*KP
    float* Ks = Qs + QT * KP;       // KT*KP
    float* Vs = Ks + KT * KP;       // KT*KP
    float* Ps = Vs + KT * KP;       // QT*PP

    int h = blockIdx.y;
    int q0 = blockIdx.x * QT;
    int tid = threadIdx.x, lane = tid & 31, warp = tid >> 5;
    const float scale = 0.11785113019775793f;   // 72^-0.5

    for (int idx = tid; idx < QT * HD; idx += 256) {
        int r = idx / HD, d = idx - r * HD;
        Qs[r * KP + d] = Q[(size_t)(q0 + r) * H + h * HD + d];
    }

    int s0[8], s1[8];
    float mrow[8], lrow[8], o[8][3];
#pragma unroll
    for (int i = 0; i < 8; ++i) {
        int qg = q0 + warp * 8 + i;
        s0[i] = segs[qg];
        s1[i] = sege[qg];
        mrow[i] = -3.0e38f;
        lrow[i] = 0.f;
        o[i][0] = o[i][1] = o[i][2] = 0.f;
    }

    int kstart = segs[q0];
    int kend = sege[q0 + QT - 1];
    int d2ok = (lane + 64 < HD);

    for (int c0 = kstart; c0 < kend; c0 += KT) {
        int len = min(KT, kend - c0);
        __syncthreads();
        for (int idx = tid; idx < KT * HD; idx += 256) {
            int r = idx / HD, d = idx - r * HD;
            float kv = 0.f, vv = 0.f;
            if (r < len) {
                size_t g = (size_t)(c0 + r) * H + h * HD + d;
                kv = Km[g];
                vv = V[g];
            }
            Ks[r * KP + d] = kv;
            Vs[r * KP + d] = vv;
        }
        __syncthreads();

        float sc[8][2];
#pragma unroll
        for (int i = 0; i < 8; ++i) { sc[i][0] = 0.f; sc[i][1] = 0.f; }
        const float* qb = Qs + (warp * 8) * KP;
        for (int d = 0; d < HD; ++d) {
            float k0v = Ks[lane * KP + d];
            float k1v = Ks[(lane + 32) * KP + d];
#pragma unroll
            for (int i = 0; i < 8; ++i) {
                float qd = qb[i * KP + d];
                sc[i][0] = fmaf(qd, k0v, sc[i][0]);
                sc[i][1] = fmaf(qd, k1v, sc[i][1]);
            }
        }

        int kg0 = c0 + lane, kg1 = c0 + lane + 32;
#pragma unroll
        for (int i = 0; i < 8; ++i) {
            bool v0ok = (kg0 >= s0[i]) && (kg0 < s1[i]);
            bool v1ok = (kg1 >= s0[i]) && (kg1 < s1[i]);
            float v0 = v0ok ? sc[i][0] * scale : -3.0e38f;
            float v1 = v1ok ? sc[i][1] * scale : -3.0e38f;
            float mx = fmaxf(v0, v1);
#pragma unroll
            for (int ofs = 16; ofs > 0; ofs >>= 1)
                mx = fmaxf(mx, __shfl_xor_sync(0xffffffffu, mx, ofs));
            float mnew = fmaxf(mrow[i], mx);
            float p0 = v0ok ? __expf(v0 - mnew) : 0.f;
            float p1 = v1ok ? __expf(v1 - mnew) : 0.f;
            float ps = p0 + p1;
#pragma unroll
            for (int ofs = 16; ofs > 0; ofs >>= 1)
                ps += __shfl_xor_sync(0xffffffffu, ps, ofs);
            float corr = __expf(mrow[i] - mnew);
            lrow[i] = lrow[i] * corr + ps;
            mrow[i] = mnew;
            o[i][0] *= corr; o[i][1] *= corr; o[i][2] *= corr;
            Ps[(warp * 8 + i) * PP + lane] = p0;
            Ps[(warp * 8 + i) * PP + lane + 32] = p1;
        }
        __syncwarp();

        for (int k = 0; k < len; ++k) {
            float vv0 = Vs[k * KP + lane];
            float vv1 = Vs[k * KP + lane + 32];
            float vv2 = d2ok ? Vs[k * KP + lane + 64] : 0.f;
#pragma unroll
            for (int i = 0; i < 8; ++i) {
                float p = Ps[(warp * 8 + i) * PP + k];
                o[i][0] = fmaf(p, vv0, o[i][0]);
                o[i][1] = fmaf(p, vv1, o[i][1]);
                o[i][2] = fmaf(p, vv2, o[i][2]);
            }
        }
    }

#pragma unroll
    for (int i = 0; i < 8; ++i) {
        float inv = 1.f / lrow[i];
        size_t base = (size_t)(q0 + warp * 8 + i) * H + h * HD;
        O[base + lane] = __float2half(o[i][0] * inv);
        O[base + lane + 32] = __float2half(o[i][1] * inv);
        if (d2ok) O[base + lane + 64] = __float2half(o[i][2] * inv);
    }
}

// ---------------- launch ----------------
extern "C" void kernel_launch(void* const* d_in, const int* in_sizes, int n_in,
                              void* d_out, int out_size) {
    const float* hs    = (const float*)d_in[0];
    const int*   doc   = (const int*)d_in[1];
    const float* q_w   = (const float*)d_in[2];
    const float* q_b   = (const float*)d_in[3];
    const float* k_w   = (const float*)d_in[4];
    const float* k_b   = (const float*)d_in[5];
    const float* v_w   = (const float*)d_in[6];
    const float* v_b   = (const float*)d_in[7];
    const float* o_w   = (const float*)d_in[8];
    const float* o_b   = (const float*)d_in[9];
    const float* ln1_g = (const float*)d_in[10];
    const float* ln1_b = (const float*)d_in[11];
    const float* ln2_g = (const float*)d_in[12];
    const float* ln2_b = (const float*)d_in[13];
    const float* fc1_w = (const float*)d_in[14];
    const float* fc1_b = (const float*)d_in[15];
    const float* fc2_w = (const float*)d_in[16];
    const float* fc2_b = (const float*)d_in[17];
    float* out = (float*)d_out;

    __half *xnh, *attnh, *yh, *ffh, *qwh, *kwh, *vwh, *owh, *fc1h, *fc2h;
    float *q, *k, *v, *hid;
    int *segs, *sege;
    cudaGetSymbolAddress((void**)&xnh,   g_xnh);
    cudaGetSymbolAddress((void**)&q,     g_q);
    cudaGetSymbolAddress((void**)&k,     g_k);
    cudaGetSymbolAddress((void**)&v,     g_v);
    cudaGetSymbolAddress((void**)&attnh, g_attnh);
    cudaGetSymbolAddress((void**)&hid,   g_hid);
    cudaGetSymbolAddress((void**)&yh,    g_yh);
    cudaGetSymbolAddress((void**)&ffh,   g_ffh);
    cudaGetSymbolAddress((void**)&qwh,   g_qwh);
    cudaGetSymbolAddress((void**)&kwh,   g_kwh);
    cudaGetSymbolAddress((void**)&vwh,   g_vwh);
    cudaGetSymbolAddress((void**)&owh,   g_owh);
    cudaGetSymbolAddress((void**)&fc1h,  g_fc1h);
    cudaGetSymbolAddress((void**)&fc2h,  g_fc2h);
    cudaGetSymbolAddress((void**)&segs,  g_segs);
    cudaGetSymbolAddress((void**)&sege,  g_sege);

    int att_smem = (QT * KP + 2 * KT * KP + QT * PP) * (int)sizeof(float);
    cudaFuncSetAttribute(attn_tile, cudaFuncAttributeMaxDynamicSharedMemorySize, att_smem);

    // weight conversion (per-launch; deterministic)
    int nHH4 = H * H / 4;
    int nHF4 = H * FF / 4;
    cvt_f2h<<<(nHH4 + 255) / 256, 256>>>((const float4*)q_w,  (__half2*)qwh,  nHH4);
    cvt_f2h<<<(nHH4 + 255) / 256, 256>>>((const float4*)k_w,  (__half2*)kwh,  nHH4);
    cvt_f2h<<<(nHH4 + 255) / 256, 256>>>((const float4*)v_w,  (__half2*)vwh,  nHH4);
    cvt_f2h<<<(nHH4 + 255) / 256, 256>>>((const float4*)o_w,  (__half2*)owh,  nHH4);
    cvt_f2h<<<(nHF4 + 255) / 256, 256>>>((const float4*)fc1_w, (__half2*)fc1h, nHF4);
    cvt_f2h<<<(nHF4 + 255) / 256, 256>>>((const float4*)fc2_w, (__half2*)fc2h, nHF4);

    dim3 gH(H / BN, S / BM);                 // (9, 32)
    dim3 gF((FF + BN - 1) / BN, S / BM);     // (34, 32)

    ln_kernel_h<<<S, 256>>>(hs, ln1_g, ln1_b, xnh);
    doc_ranges<<<(S + 255) / 256, 256>>>(doc, segs, sege);

    gemm_f16<<<gH, 256>>>(xnh, qwh, q_b, nullptr, q, nullptr, S, H, H, 0);
    gemm_f16<<<gH, 256>>>(xnh, kwh, k_b, nullptr, k, nullptr, S, H, H, 0);
    gemm_f16<<<gH, 256>>>(xnh, vwh, v_b, nullptr, v, nullptr, S, H, H, 0);

    attn_tile<<<dim3(S / QT, NH), 256, att_smem>>>(q, k, v, segs, sege, attnh);

    gemm_f16<<<gH, 256>>>(attnh, owh, o_b, hs, hid, nullptr, S, H, H, 2);

    ln_kernel_h<<<S, 256>>>(hid, ln2_g, ln2_b, yh);

    gemm_f16<<<gF, 256>>>(yh, fc1h, fc1_b, nullptr, nullptr, ffh, S, FF, H, 1);
    gemm_f16<<<gH, 256>>>(ffh, fc2h, fc2_b, hid, out, nullptr, S, H, FF, 2);
}

// round 10
// speedup vs baseline: 8.0906x; 1.1778x over previous
#include <cuda_runtime.h>
#include <cuda_fp16.h>
#include <math.h>
#include <stdint.h>

#define S 4096
#define H 1152
#define NH 16
#define HD 72
#define FF 4304
#define LN_EPS 1e-6f

// ---------------- scratch (allocation-free: device globals) ----------------
__device__ __half g_xnh[S * H];
__device__ __half g_qh[S * H];
__device__ __half g_kh[S * H];
__device__ __half g_vh[S * H];
__device__ __half g_attnh[S * H];
__device__ float  g_hid[S * H];
__device__ __half g_yh[S * H];
__device__ __half g_ffh[(size_t)S * FF];
__device__ __half g_qwh[H * H];
__device__ __half g_kwh[H * H];
__device__ __half g_vwh[H * H];
__device__ __half g_owh[H * H];
__device__ __half g_fc1h[(size_t)H * FF];
__device__ __half g_fc2h[(size_t)H * FF];
__device__ int g_segs[S];
__device__ int g_sege[S];

// ---------------- weight conversion: float -> half ----------------
__global__ __launch_bounds__(256) void cvt_f2h(const float4* __restrict__ x,
                                               __half2* __restrict__ y, int n4) {
    int i = blockIdx.x * blockDim.x + threadIdx.x;
    if (i < n4) {
        float4 v = x[i];
        y[2 * i]     = __floats2half2_rn(v.x, v.y);
        y[2 * i + 1] = __floats2half2_rn(v.z, v.w);
    }
}

// 4 same-size tensors in one launch (blockIdx.y selects)
__global__ __launch_bounds__(256) void cvt_f2h4(const float4* __restrict__ x0,
                                                const float4* __restrict__ x1,
                                                const float4* __restrict__ x2,
                                                const float4* __restrict__ x3,
                                                __half2* __restrict__ y0,
                                                __half2* __restrict__ y1,
                                                __half2* __restrict__ y2,
                                                __half2* __restrict__ y3,
                                                int n4) {
    int i = blockIdx.x * blockDim.x + threadIdx.x;
    if (i >= n4) return;
    const float4* x; __half2* y;
    switch (blockIdx.y) {
        case 0: x = x0; y = y0; break;
        case 1: x = x1; y = y1; break;
        case 2: x = x2; y = y2; break;
        default: x = x3; y = y3; break;
    }
    float4 v = x[i];
    y[2 * i]     = __floats2half2_rn(v.x, v.y);
    y[2 * i + 1] = __floats2half2_rn(v.z, v.w);
}

// ---------------- LayerNorm: one block per row, half output ----------------
__global__ __launch_bounds__(256) void ln_kernel_h(const float* __restrict__ x,
                                                   const float* __restrict__ g,
                                                   const float* __restrict__ b,
                                                   __half* __restrict__ y) {
    int row = blockIdx.x;
    const float* xr = x + (size_t)row * H;
    __shared__ float red[256];
    int tid = threadIdx.x;

    float s = 0.f;
    for (int i = tid; i < H; i += 256) s += xr[i];
    red[tid] = s;
    __syncthreads();
    for (int off = 128; off > 0; off >>= 1) {
        if (tid < off) red[tid] += red[tid + off];
        __syncthreads();
    }
    float mu = red[0] * (1.0f / H);
    __syncthreads();

    float sq = 0.f;
    for (int i = tid; i < H; i += 256) {
        float d = xr[i] - mu;
        sq += d * d;
    }
    red[tid] = sq;
    __syncthreads();
    for (int off = 128; off > 0; off >>= 1) {
        if (tid < off) red[tid] += red[tid + off];
        __syncthreads();
    }
    float inv = rsqrtf(red[0] * (1.0f / H) + LN_EPS);

    __half* yr = y + (size_t)row * H;
    for (int i = tid; i < H; i += 256)
        yr[i] = __float2half((xr[i] - mu) * inv * g[i] + b[i]);
}

// ---------------- document segment ranges (ids are sorted) ----------------
__global__ void doc_ranges(const int* __restrict__ ids, int* __restrict__ segs,
                           int* __restrict__ sege) {
    int i = blockIdx.x * blockDim.x + threadIdx.x;
    if (i >= S) return;
    int d = ids[i];
    int lo = 0, hi = S;
    while (lo < hi) { int mid = (lo + hi) >> 1; if (ids[mid] < d) lo = mid + 1; else hi = mid; }
    segs[i] = lo;
    lo = 0; hi = S;
    while (lo < hi) { int mid = (lo + hi) >> 1; if (ids[mid] <= d) lo = mid + 1; else hi = mid; }
    sege[i] = lo;
}

// ---------------- common mma ----------------
__device__ __forceinline__ void mma_f16(float* c, const uint32_t* a, const uint32_t* b) {
    asm volatile(
        "mma.sync.aligned.m16n8k16.row.col.f32.f16.f16.f32 "
        "{%0,%1,%2,%3}, {%4,%5,%6,%7}, {%8,%9}, {%0,%1,%2,%3};"
        : "+f"(c[0]), "+f"(c[1]), "+f"(c[2]), "+f"(c[3])
        : "r"(a[0]), "r"(a[1]), "r"(a[2]), "r"(a[3]), "r"(b[0]), "r"(b[1]));
}

// ---------------- FP16 tensor-core GEMM (unchanged from R9 pass) -----------
#define BM 128
#define BN 128
#define BKH 32
#define PITCH 40

__device__ __forceinline__ void cp16(void* dst, const void* src, bool valid,
                                     const void* safe) {
    uint32_t d = (uint32_t)__cvta_generic_to_shared(dst);
    const void* s = valid ? src : safe;   // always in-bounds address
    int sz = valid ? 16 : 0;
    asm volatile("cp.async.cg.shared.global [%0], [%1], 16, %2;\n"
                 :: "r"(d), "l"(s), "r"(sz));
}

__global__ __launch_bounds__(256, 2) void gemm_f16(const __half* __restrict__ A,
                                                   const __half* __restrict__ W,
                                                   const float* __restrict__ bias,
                                                   const float* __restrict__ res,
                                                   float* __restrict__ C,
                                                   __half* __restrict__ Ch,
                                                   int M, int N, int K, int epi) {
    __shared__ __half As[2][BM][PITCH];
    __shared__ __half Ws[2][BN][PITCH];

    int tid = threadIdx.x;
    int lane = tid & 31, warp = tid >> 5;
    int wn = warp & 3;
    int wm = warp >> 2;
    int m0 = blockIdx.y * BM;
    int n0 = blockIdx.x * BN;

    int lr = tid >> 1;
    int lc = (tid & 1) * 2;

    const __half* Ab = A + (size_t)m0 * K;

    float acc[4][4][4];
#pragma unroll
    for (int i = 0; i < 4; ++i)
#pragma unroll
        for (int j = 0; j < 4; ++j)
#pragma unroll
            for (int l = 0; l < 4; ++l) acc[i][j][l] = 0.f;

    int nk = (K + BKH - 1) / BKH;

    {
#pragma unroll
        for (int cc = 0; cc < 2; ++cc) {
            int c = lc + cc;
            cp16(&As[0][lr][c * 8], Ab + (size_t)lr * K + c * 8,
                 (c * 8 + 8 <= K), A);
            cp16(&Ws[0][lr][c * 8], W + (size_t)(n0 + lr) * K + c * 8,
                 ((n0 + lr) < N) && (c * 8 + 8 <= K), W);
        }
    }
    asm volatile("cp.async.commit_group;\n" ::: "memory");

    int fr = lane >> 2;
    int fc = lane & 3;

    for (int t = 0; t < nk; ++t) {
        asm volatile("cp.async.wait_group 0;\n" ::: "memory");
        __syncthreads();

        int st = t & 1;
        if (t + 1 < nk) {
            int ko = (t + 1) * BKH;
#pragma unroll
            for (int cc = 0; cc < 2; ++cc) {
                int c = lc + cc;
                cp16(&As[st ^ 1][lr][c * 8], Ab + (size_t)lr * K + ko + c * 8,
                     (ko + c * 8 + 8 <= K), A);
                cp16(&Ws[st ^ 1][lr][c * 8], W + (size_t)(n0 + lr) * K + ko + c * 8,
                     ((n0 + lr) < N) && (ko + c * 8 + 8 <= K), W);
            }
        }
        asm volatile("cp.async.commit_group;\n" ::: "memory");

#pragma unroll
        for (int kk = 0; kk < 2; ++kk) {
            int kb = kk * 16;
            uint32_t a[4][4], b[4][2];
#pragma unroll
            for (int mt = 0; mt < 4; ++mt) {
                int mr = wm * 64 + mt * 16;
                a[mt][0] = *(const uint32_t*)&As[st][mr + fr][kb + fc * 2];
                a[mt][1] = *(const uint32_t*)&As[st][mr + fr + 8][kb + fc * 2];
                a[mt][2] = *(const uint32_t*)&As[st][mr + fr][kb + fc * 2 + 8];
                a[mt][3] = *(const uint32_t*)&As[st][mr + fr + 8][kb + fc * 2 + 8];
            }
#pragma unroll
            for (int nt = 0; nt < 4; ++nt) {
                int nr = wn * 32 + nt * 8;
                b[nt][0] = *(const uint32_t*)&Ws[st][nr + fr][kb + fc * 2];
                b[nt][1] = *(const uint32_t*)&Ws[st][nr + fr][kb + fc * 2 + 8];
            }
#pragma unroll
            for (int mt = 0; mt < 4; ++mt)
#pragma unroll
                for (int nt = 0; nt < 4; ++nt)
                    mma_f16(acc[mt][nt], a[mt], b[nt]);
        }
    }

#pragma unroll
    for (int mt = 0; mt < 4; ++mt) {
        int row = m0 + wm * 64 + mt * 16 + fr;
#pragma unroll
        for (int nt = 0; nt < 4; ++nt) {
            int col = n0 + wn * 32 + nt * 8 + fc * 2;
#pragma unroll
            for (int l = 0; l < 4; ++l) {
                int r = row + ((l >> 1) ? 8 : 0);
                int c = col + (l & 1);
                if (c >= N) continue;
                float v = acc[mt][nt][l] + bias[c];
                if (epi == 1) {
                    float u = 0.7978845608028654f * (v + 0.044715f * v * v * v);
                    float e = __expf(2.f * u);
                    float th = 1.f - 2.f / (e + 1.f);
                    v = 0.5f * v * (1.0f + th);
                } else if (epi == 2) {
                    v += res[(size_t)r * N + c];
                }
                if (Ch) Ch[(size_t)r * N + c] = __float2half(v);
                else    C[(size_t)r * N + c] = v;
            }
        }
    }
}

// ---------------- tensor-core flash attention (doc-masked) -----------------
// Block: 64 queries x 1 head, 128 threads (4 warps x 16 rows). K chunks of 64.
#define AQT 64
#define AKT 64
#define QKP 88   // pitch (halves) for Qs/Ks: (12*fr+fc)%32 bijective
#define VTP 72   // pitch (halves) for Vt:    (4*fr+fc)%32 bijective

__global__ __launch_bounds__(128) void attn_mma(const __half* __restrict__ Q,
                                                const __half* __restrict__ K,
                                                const __half* __restrict__ V,
                                                const int* __restrict__ segs,
                                                const int* __restrict__ sege,
                                                __half* __restrict__ O) {
    __shared__ __half Qs[AQT][QKP];
    __shared__ __half Ks[AKT][QKP];
    __shared__ __half Vt[HD][VTP];   // transposed V: [dim][key]

    int h = blockIdx.y;
    int q0 = blockIdx.x * AQT;
    int tid = threadIdx.x, lane = tid & 31, warp = tid >> 5;
    int fr = lane >> 2, fc = lane & 3;
    const float scale = 0.11785113019775793f;   // 72^-0.5

    // zero-init all smem (pads must be 0; avoids NaN/Inf garbage in tails)
    {
        uint4 z = make_uint4(0, 0, 0, 0);
        uint4* p0 = (uint4*)&Qs[0][0];
        int n = (AQT * QKP * 2 + AKT * QKP * 2 + HD * VTP * 2);
        // Qs,Ks,Vt are contiguous declarations but not guaranteed adjacent;
        // zero each explicitly.
        for (int i = tid; i < AQT * QKP / 8; i += 128) ((uint4*)&Qs[0][0])[i] = z;
        for (int i = tid; i < AKT * QKP / 8; i += 128) ((uint4*)&Ks[0][0])[i] = z;
        for (int i = tid; i < HD * VTP / 8; i += 128) ((uint4*)&Vt[0][0])[i] = z;
        (void)p0; (void)n;
    }
    __syncthreads();

    // stage Q tile: 64 rows x 72 halves (9 x uint4 per row)
    for (int i = tid; i < AQT * 9; i += 128) {
        int r = i / 9, c = i - r * 9;
        *(uint4*)&Qs[r][c * 8] =
            *(const uint4*)&Q[(size_t)(q0 + r) * H + h * HD + c * 8];
    }

    // per-thread rows: r0 = warp*16+fr, r1 = r0+8 (local tile rows)
    int rs0[2], rs1[2];
    rs0[0] = segs[q0 + warp * 16 + fr];     rs1[0] = sege[q0 + warp * 16 + fr];
    rs0[1] = segs[q0 + warp * 16 + fr + 8]; rs1[1] = sege[q0 + warp * 16 + fr + 8];
    float m[2] = {-3.0e38f, -3.0e38f};
    float l[2] = {0.f, 0.f};
    float out[9][4];
#pragma unroll
    for (int nt = 0; nt < 9; ++nt)
#pragma unroll
        for (int i = 0; i < 4; ++i) out[nt][i] = 0.f;

    int kstart = segs[q0];
    int kend = sege[q0 + AQT - 1];

    for (int c0 = kstart; c0 < kend; c0 += AKT) {
        int len = min(AKT, kend - c0);
        __syncthreads();   // previous chunk fully consumed

        for (int i = tid; i < len * 9; i += 128) {
            int r = i / 9, c = i - r * 9;
            *(uint4*)&Ks[r][c * 8] =
                *(const uint4*)&K[(size_t)(c0 + r) * H + h * HD + c * 8];
        }
        for (int i = tid; i < len * HD; i += 128) {
            int r = i / HD, d = i - r * HD;
            Vt[d][r] = V[(size_t)(c0 + r) * H + h * HD + d];
        }
        __syncthreads();

        // ---- S = Q @ K^T  (per warp: 16 rows x 64 keys; k=80 incl. zero pad)
        float sc[8][4];
#pragma unroll
        for (int nt = 0; nt < 8; ++nt)
#pragma unroll
            for (int i = 0; i < 4; ++i) sc[nt][i] = 0.f;

#pragma unroll
        for (int kk = 0; kk < 5; ++kk) {
            int kb = kk * 16;
            uint32_t a[4];
            a[0] = *(const uint32_t*)&Qs[warp * 16 + fr][kb + fc * 2];
            a[1] = *(const uint32_t*)&Qs[warp * 16 + fr + 8][kb + fc * 2];
            a[2] = *(const uint32_t*)&Qs[warp * 16 + fr][kb + fc * 2 + 8];
            a[3] = *(const uint32_t*)&Qs[warp * 16 + fr + 8][kb + fc * 2 + 8];
#pragma unroll
            for (int nt = 0; nt < 8; ++nt) {
                uint32_t b[2];
                b[0] = *(const uint32_t*)&Ks[nt * 8 + fr][kb + fc * 2];
                b[1] = *(const uint32_t*)&Ks[nt * 8 + fr][kb + fc * 2 + 8];
                mma_f16(sc[nt], a, b);
            }
        }

        // ---- mask + scale; row max
        float mx0 = -3.0e38f, mx1 = -3.0e38f;
#pragma unroll
        for (int nt = 0; nt < 8; ++nt) {
            int kg0 = c0 + nt * 8 + fc * 2;
            int kg1 = kg0 + 1;
            sc[nt][0] = (kg0 >= rs0[0] && kg0 < rs1[0]) ? sc[nt][0] * scale : -3.0e38f;
            sc[nt][1] = (kg1 >= rs0[0] && kg1 < rs1[0]) ? sc[nt][1] * scale : -3.0e38f;
            sc[nt][2] = (kg0 >= rs0[1] && kg0 < rs1[1]) ? sc[nt][2] * scale : -3.0e38f;
            sc[nt][3] = (kg1 >= rs0[1] && kg1 < rs1[1]) ? sc[nt][3] * scale : -3.0e38f;
            mx0 = fmaxf(mx0, fmaxf(sc[nt][0], sc[nt][1]));
            mx1 = fmaxf(mx1, fmaxf(sc[nt][2], sc[nt][3]));
        }
#pragma unroll
        for (int ofs = 1; ofs <= 2; ofs <<= 1) {
            mx0 = fmaxf(mx0, __shfl_xor_sync(0xffffffffu, mx0, ofs));
            mx1 = fmaxf(mx1, __shfl_xor_sync(0xffffffffu, mx1, ofs));
        }
        float mnew0 = fmaxf(m[0], mx0);
        float mnew1 = fmaxf(m[1], mx1);
        float corr0 = __expf(m[0] - mnew0);
        float corr1 = __expf(m[1] - mnew1);

        // ---- p = exp(s - mnew); row sums (sentinel guard handles all-masked)
        float ps0 = 0.f, ps1 = 0.f;
#pragma unroll
        for (int nt = 0; nt < 8; ++nt) {
            sc[nt][0] = (sc[nt][0] > -1.0e38f) ? __expf(sc[nt][0] - mnew0) : 0.f;
            sc[nt][1] = (sc[nt][1] > -1.0e38f) ? __expf(sc[nt][1] - mnew0) : 0.f;
            sc[nt][2] = (sc[nt][2] > -1.0e38f) ? __expf(sc[nt][2] - mnew1) : 0.f;
            sc[nt][3] = (sc[nt][3] > -1.0e38f) ? __expf(sc[nt][3] - mnew1) : 0.f;
            ps0 += sc[nt][0] + sc[nt][1];
            ps1 += sc[nt][2] + sc[nt][3];
        }
#pragma unroll
        for (int ofs = 1; ofs <= 2; ofs <<= 1) {
            ps0 += __shfl_xor_sync(0xffffffffu, ps0, ofs);
            ps1 += __shfl_xor_sync(0xffffffffu, ps1, ofs);
        }
        l[0] = l[0] * corr0 + ps0;
        l[1] = l[1] * corr1 + ps1;
        m[0] = mnew0;
        m[1] = mnew1;

        // ---- rescale out, pack p to half, PV mma
#pragma unroll
        for (int nt = 0; nt < 9; ++nt) {
            out[nt][0] *= corr0; out[nt][1] *= corr0;
            out[nt][2] *= corr1; out[nt][3] *= corr1;
        }
        uint32_t pr0[8], pr1[8];
#pragma unroll
        for (int nt = 0; nt < 8; ++nt) {
            __half2 h0 = __floats2half2_rn(sc[nt][0], sc[nt][1]);
            __half2 h1 = __floats2half2_rn(sc[nt][2], sc[nt][3]);
            pr0[nt] = *(uint32_t*)&h0;
            pr1[nt] = *(uint32_t*)&h1;
        }
#pragma unroll
        for (int j = 0; j < 4; ++j) {
            uint32_t a[4] = {pr0[2 * j], pr1[2 * j], pr0[2 * j + 1], pr1[2 * j + 1]};
            int kb = j * 16;
#pragma unroll
            for (int nt = 0; nt < 9; ++nt) {
                uint32_t b[2];
                b[0] = *(const uint32_t*)&Vt[nt * 8 + fr][kb + fc * 2];
                b[1] = *(const uint32_t*)&Vt[nt * 8 + fr][kb + fc * 2 + 8];
                mma_f16(out[nt], a, b);
            }
        }
    }

    // ---- store: out / l  (half2 per fragment pair)
    float inv0 = 1.f / l[0];
    float inv1 = 1.f / l[1];
    size_t base0 = (size_t)(q0 + warp * 16 + fr) * H + h * HD;
    size_t base1 = (size_t)(q0 + warp * 16 + fr + 8) * H + h * HD;
#pragma unroll
    for (int nt = 0; nt < 9; ++nt) {
        int col = nt * 8 + fc * 2;
        __half2 o0 = __floats2half2_rn(out[nt][0] * inv0, out[nt][1] * inv0);
        __half2 o1 = __floats2half2_rn(out[nt][2] * inv1, out[nt][3] * inv1);
        *(__half2*)&O[base0 + col] = o0;
        *(__half2*)&O[base1 + col] = o1;
    }
}

// ---------------- launch ----------------
extern "C" void kernel_launch(void* const* d_in, const int* in_sizes, int n_in,
                              void* d_out, int out_size) {
    const float* hs    = (const float*)d_in[0];
    const int*   doc   = (const int*)d_in[1];
    const float* q_w   = (const float*)d_in[2];
    const float* q_b   = (const float*)d_in[3];
    const float* k_w   = (const float*)d_in[4];
    const float* k_b   = (const float*)d_in[5];
    const float* v_w   = (const float*)d_in[6];
    const float* v_b   = (const float*)d_in[7];
    const float* o_w   = (const float*)d_in[8];
    const float* o_b   = (const float*)d_in[9];
    const float* ln1_g = (const float*)d_in[10];
    const float* ln1_b = (const float*)d_in[11];
    const float* ln2_g = (const float*)d_in[12];
    const float* ln2_b = (const float*)d_in[13];
    const float* fc1_w = (const float*)d_in[14];
    const float* fc1_b = (const float*)d_in[15];
    const float* fc2_w = (const float*)d_in[16];
    const float* fc2_b = (const float*)d_in[17];
    float* out = (float*)d_out;

    __half *xnh, *qh, *kh, *vh, *attnh, *yh, *ffh;
    __half *qwh, *kwh, *vwh, *owh, *fc1h, *fc2h;
    float *hid;
    int *segs, *sege;
    cudaGetSymbolAddress((void**)&xnh,   g_xnh);
    cudaGetSymbolAddress((void**)&qh,    g_qh);
    cudaGetSymbolAddress((void**)&kh,    g_kh);
    cudaGetSymbolAddress((void**)&vh,    g_vh);
    cudaGetSymbolAddress((void**)&attnh, g_attnh);
    cudaGetSymbolAddress((void**)&hid,   g_hid);
    cudaGetSymbolAddress((void**)&yh,    g_yh);
    cudaGetSymbolAddress((void**)&ffh,   g_ffh);
    cudaGetSymbolAddress((void**)&qwh,   g_qwh);
    cudaGetSymbolAddress((void**)&kwh,   g_kwh);
    cudaGetSymbolAddress((void**)&vwh,   g_vwh);
    cudaGetSymbolAddress((void**)&owh,   g_owh);
    cudaGetSymbolAddress((void**)&fc1h,  g_fc1h);
    cudaGetSymbolAddress((void**)&fc2h,  g_fc2h);
    cudaGetSymbolAddress((void**)&segs,  g_segs);
    cudaGetSymbolAddress((void**)&sege,  g_sege);

    // weight conversion
    int nHH4 = H * H / 4;
    int nHF4 = H * FF / 4;
    cvt_f2h4<<<dim3((nHH4 + 255) / 256, 4), 256>>>(
        (const float4*)q_w, (const float4*)k_w, (const float4*)v_w, (const float4*)o_w,
        (__half2*)qwh, (__half2*)kwh, (__half2*)vwh, (__half2*)owh, nHH4);
    cvt_f2h<<<(nHF4 + 255) / 256, 256>>>((const float4*)fc1_w, (__half2*)fc1h, nHF4);
    cvt_f2h<<<(nHF4 + 255) / 256, 256>>>((const float4*)fc2_w, (__half2*)fc2h, nHF4);

    dim3 gH(H / BN, S / BM);                 // (9, 32)
    dim3 gF((FF + BN - 1) / BN, S / BM);     // (34, 32)

    ln_kernel_h<<<S, 256>>>(hs, ln1_g, ln1_b, xnh);
    doc_ranges<<<(S + 255) / 256, 256>>>(doc, segs, sege);

    gemm_f16<<<gH, 256>>>(xnh, qwh, q_b, nullptr, nullptr, qh, S, H, H, 0);
    gemm_f16<<<gH, 256>>>(xnh, kwh, k_b, nullptr, nullptr, kh, S, H, H, 0);
    gemm_f16<<<gH, 256>>>(xnh, vwh, v_b, nullptr, nullptr, vh, S, H, H, 0);

    attn_mma<<<dim3(S / AQT, NH), 128>>>(qh, kh, vh, segs, sege, attnh);

    gemm_f16<<<gH, 256>>>(attnh, owh, o_b, hs, hid, nullptr, S, H, H, 2);

    ln_kernel_h<<<S, 256>>>(hid, ln2_g, ln2_b, yh);

    gemm_f16<<<gF, 256>>>(yh, fc1h, fc1_b, nullptr, nullptr, ffh, S, FF, H, 1);
    gemm_f16<<<gH, 256>>>(ffh, fc2h, fc2_b, hid, out, nullptr, S, H, FF, 2);
}

// round 11
// speedup vs baseline: 8.4494x; 1.0444x over previous
#include <cuda_runtime.h>
#include <cuda_fp16.h>
#include <math.h>
#include <stdint.h>

#define S 4096
#define H 1152
#define NH 16
#define HD 72
#define FF 4304
#define QKVN (3 * H)          // 3456
#define LN_EPS 1e-6f

// ---------------- scratch (allocation-free: device globals) ----------------
__device__ __half g_xnh[S * H];
__device__ __half g_qkvh[(size_t)S * QKVN];
__device__ __half g_attnh[S * H];
__device__ float  g_hid[S * H];
__device__ __half g_yh[S * H];
__device__ __half g_ffh[(size_t)S * FF];
__device__ __half g_wqkvh[(size_t)QKVN * H];
__device__ __half g_owh[H * H];
__device__ __half g_fc1h[(size_t)H * FF];
__device__ __half g_fc2h[(size_t)H * FF];
__device__ float  g_bqkv[QKVN];
__device__ int g_segs[S];
__device__ int g_sege[S];

// ---------------- weight conversion: float -> half ----------------
__global__ __launch_bounds__(256) void cvt_f2h(const float4* __restrict__ x,
                                               __half2* __restrict__ y, int n4) {
    int i = blockIdx.x * blockDim.x + threadIdx.x;
    if (i < n4) {
        float4 v = x[i];
        y[2 * i]     = __floats2half2_rn(v.x, v.y);
        y[2 * i + 1] = __floats2half2_rn(v.z, v.w);
    }
}

// 4 same-size tensors in one launch (blockIdx.y selects)
__global__ __launch_bounds__(256) void cvt_f2h4(const float4* __restrict__ x0,
                                                const float4* __restrict__ x1,
                                                const float4* __restrict__ x2,
                                                const float4* __restrict__ x3,
                                                __half2* __restrict__ y0,
                                                __half2* __restrict__ y1,
                                                __half2* __restrict__ y2,
                                                __half2* __restrict__ y3,
                                                int n4) {
    int i = blockIdx.x * blockDim.x + threadIdx.x;
    if (i >= n4) return;
    const float4* x; __half2* y;
    switch (blockIdx.y) {
        case 0: x = x0; y = y0; break;
        case 1: x = x1; y = y1; break;
        case 2: x = x2; y = y2; break;
        default: x = x3; y = y3; break;
    }
    float4 v = x[i];
    y[2 * i]     = __floats2half2_rn(v.x, v.y);
    y[2 * i + 1] = __floats2half2_rn(v.z, v.w);
}

__global__ __launch_bounds__(256) void pack_bias(const float* __restrict__ qb,
                                                 const float* __restrict__ kb,
                                                 const float* __restrict__ vb,
                                                 float* __restrict__ dst) {
    int i = blockIdx.x * blockDim.x + threadIdx.x;
    if (i < H) {
        dst[i] = qb[i];
        dst[H + i] = kb[i];
        dst[2 * H + i] = vb[i];
    }
}

// ---------------- LayerNorm: one block per row, half output ----------------
__global__ __launch_bounds__(256) void ln_kernel_h(const float* __restrict__ x,
                                                   const float* __restrict__ g,
                                                   const float* __restrict__ b,
                                                   __half* __restrict__ y) {
    int row = blockIdx.x;
    const float* xr = x + (size_t)row * H;
    __shared__ float red[256];
    int tid = threadIdx.x;

    float s = 0.f;
    for (int i = tid; i < H; i += 256) s += xr[i];
    red[tid] = s;
    __syncthreads();
    for (int off = 128; off > 0; off >>= 1) {
        if (tid < off) red[tid] += red[tid + off];
        __syncthreads();
    }
    float mu = red[0] * (1.0f / H);
    __syncthreads();

    float sq = 0.f;
    for (int i = tid; i < H; i += 256) {
        float d = xr[i] - mu;
        sq += d * d;
    }
    red[tid] = sq;
    __syncthreads();
    for (int off = 128; off > 0; off >>= 1) {
        if (tid < off) red[tid] += red[tid + off];
        __syncthreads();
    }
    float inv = rsqrtf(red[0] * (1.0f / H) + LN_EPS);

    __half* yr = y + (size_t)row * H;
    for (int i = tid; i < H; i += 256)
        yr[i] = __float2half((xr[i] - mu) * inv * g[i] + b[i]);
}

// ---------------- document segment ranges (ids are sorted) ----------------
__global__ void doc_ranges(const int* __restrict__ ids, int* __restrict__ segs,
                           int* __restrict__ sege) {
    int i = blockIdx.x * blockDim.x + threadIdx.x;
    if (i >= S) return;
    int d = ids[i];
    int lo = 0, hi = S;
    while (lo < hi) { int mid = (lo + hi) >> 1; if (ids[mid] < d) lo = mid + 1; else hi = mid; }
    segs[i] = lo;
    lo = 0; hi = S;
    while (lo < hi) { int mid = (lo + hi) >> 1; if (ids[mid] <= d) lo = mid + 1; else hi = mid; }
    sege[i] = lo;
}

// ---------------- common mma / ldmatrix ----------------
__device__ __forceinline__ void mma_f16(float* c, const uint32_t* a, const uint32_t* b) {
    asm volatile(
        "mma.sync.aligned.m16n8k16.row.col.f32.f16.f16.f32 "
        "{%0,%1,%2,%3}, {%4,%5,%6,%7}, {%8,%9}, {%0,%1,%2,%3};"
        : "+f"(c[0]), "+f"(c[1]), "+f"(c[2]), "+f"(c[3])
        : "r"(a[0]), "r"(a[1]), "r"(a[2]), "r"(a[3]), "r"(b[0]), "r"(b[1]));
}

__device__ __forceinline__ void ldm_x4(uint32_t* r, uint32_t addr) {
    asm volatile("ldmatrix.sync.aligned.m8n8.x4.shared.b16 {%0,%1,%2,%3}, [%4];"
                 : "=r"(r[0]), "=r"(r[1]), "=r"(r[2]), "=r"(r[3]) : "r"(addr));
}
__device__ __forceinline__ void ldm_x2(uint32_t* r, uint32_t addr) {
    asm volatile("ldmatrix.sync.aligned.m8n8.x2.shared.b16 {%0,%1}, [%2];"
                 : "=r"(r[0]), "=r"(r[1]) : "r"(addr));
}

// ---------------- FP16 tensor-core GEMM (ldmatrix fragments) ---------------
#define BM 128
#define BN 128
#define BKH 32
#define PITCH 40

__device__ __forceinline__ void cp16(void* dst, const void* src, bool valid,
                                     const void* safe) {
    uint32_t d = (uint32_t)__cvta_generic_to_shared(dst);
    const void* s = valid ? src : safe;   // always in-bounds address
    int sz = valid ? 16 : 0;
    asm volatile("cp.async.cg.shared.global [%0], [%1], 16, %2;\n"
                 :: "r"(d), "l"(s), "r"(sz));
}

__global__ __launch_bounds__(256, 2) void gemm_f16(const __half* __restrict__ A,
                                                   const __half* __restrict__ W,
                                                   const float* __restrict__ bias,
                                                   const float* __restrict__ res,
                                                   float* __restrict__ C,
                                                   __half* __restrict__ Ch,
                                                   int M, int N, int K, int epi) {
    __shared__ __half As[2][BM][PITCH];
    __shared__ __half Ws[2][BN][PITCH];

    int tid = threadIdx.x;
    int lane = tid & 31, warp = tid >> 5;
    int wn = warp & 3;
    int wm = warp >> 2;
    int m0 = blockIdx.y * BM;
    int n0 = blockIdx.x * BN;

    int lr = tid >> 1;
    int lc = (tid & 1) * 2;

    const __half* Ab = A + (size_t)m0 * K;

    float acc[4][4][4];
#pragma unroll
    for (int i = 0; i < 4; ++i)
#pragma unroll
        for (int j = 0; j < 4; ++j)
#pragma unroll
            for (int l = 0; l < 4; ++l) acc[i][j][l] = 0.f;

    int nk = (K + BKH - 1) / BKH;

    {
#pragma unroll
        for (int cc = 0; cc < 2; ++cc) {
            int c = lc + cc;
            cp16(&As[0][lr][c * 8], Ab + (size_t)lr * K + c * 8,
                 (c * 8 + 8 <= K), A);
            cp16(&Ws[0][lr][c * 8], W + (size_t)(n0 + lr) * K + c * 8,
                 ((n0 + lr) < N) && (c * 8 + 8 <= K), W);
        }
    }
    asm volatile("cp.async.commit_group;\n" ::: "memory");

    // ldmatrix lane-address components (bytes)
    uint32_t aRowOff = (uint32_t)((wm * 64 + (lane & 15)) * PITCH + ((lane >> 4) << 3)) * 2;
    uint32_t bRowOff = (uint32_t)((wn * 32 + (lane & 7)) * PITCH + (((lane >> 3) & 1) << 3)) * 2;

    int fr = lane >> 2;
    int fc = lane & 3;

    for (int t = 0; t < nk; ++t) {
        asm volatile("cp.async.wait_group 0;\n" ::: "memory");
        __syncthreads();

        int st = t & 1;
        if (t + 1 < nk) {
            int ko = (t + 1) * BKH;
#pragma unroll
            for (int cc = 0; cc < 2; ++cc) {
                int c = lc + cc;
                cp16(&As[st ^ 1][lr][c * 8], Ab + (size_t)lr * K + ko + c * 8,
                     (ko + c * 8 + 8 <= K), A);
                cp16(&Ws[st ^ 1][lr][c * 8], W + (size_t)(n0 + lr) * K + ko + c * 8,
                     ((n0 + lr) < N) && (ko + c * 8 + 8 <= K), W);
            }
        }
        asm volatile("cp.async.commit_group;\n" ::: "memory");

        uint32_t aSm = (uint32_t)__cvta_generic_to_shared(&As[st][0][0]) + aRowOff;
        uint32_t bSm = (uint32_t)__cvta_generic_to_shared(&Ws[st][0][0]) + bRowOff;

#pragma unroll
        for (int kk = 0; kk < 2; ++kk) {
            uint32_t kB = (uint32_t)(kk * 16 * 2);
            uint32_t a[4][4], b[4][2];
#pragma unroll
            for (int mt = 0; mt < 4; ++mt)
                ldm_x4(a[mt], aSm + kB + (uint32_t)(mt * 16 * PITCH * 2));
#pragma unroll
            for (int nt = 0; nt < 4; ++nt)
                ldm_x2(b[nt], bSm + kB + (uint32_t)(nt * 8 * PITCH * 2));
#pragma unroll
            for (int mt = 0; mt < 4; ++mt)
#pragma unroll
                for (int nt = 0; nt < 4; ++nt)
                    mma_f16(acc[mt][nt], a[mt], b[nt]);
        }
    }

#pragma unroll
    for (int mt = 0; mt < 4; ++mt) {
        int row = m0 + wm * 64 + mt * 16 + fr;
#pragma unroll
        for (int nt = 0; nt < 4; ++nt) {
            int col = n0 + wn * 32 + nt * 8 + fc * 2;
#pragma unroll
            for (int l = 0; l < 4; ++l) {
                int r = row + ((l >> 1) ? 8 : 0);
                int c = col + (l & 1);
                if (c >= N) continue;
                float v = acc[mt][nt][l] + bias[c];
                if (epi == 1) {
                    float u = 0.7978845608028654f * (v + 0.044715f * v * v * v);
                    float e = __expf(2.f * u);
                    float th = 1.f - 2.f / (e + 1.f);
                    v = 0.5f * v * (1.0f + th);
                } else if (epi == 2) {
                    v += res[(size_t)r * N + c];
                }
                if (Ch) Ch[(size_t)r * N + c] = __float2half(v);
                else    C[(size_t)r * N + c] = v;
            }
        }
    }
}

// ---------------- tensor-core flash attention (doc-masked) -----------------
// Q/K/V are slices of the packed QKV output: row stride QKVN.
#define AQT 64
#define AKT 64
#define QKP 88
#define VTP 72

__global__ __launch_bounds__(128) void attn_mma(const __half* __restrict__ QKV,
                                                const int* __restrict__ segs,
                                                const int* __restrict__ sege,
                                                __half* __restrict__ O) {
    __shared__ __half Qs[AQT][QKP];
    __shared__ __half Ks[AKT][QKP];
    __shared__ __half Vt[HD][VTP];

    int h = blockIdx.y;
    int q0 = blockIdx.x * AQT;
    int tid = threadIdx.x, lane = tid & 31, warp = tid >> 5;
    int fr = lane >> 2, fc = lane & 3;
    const float scale = 0.11785113019775793f;

    const __half* Q = QKV + h * HD;
    const __half* K = QKV + H + h * HD;
    const __half* V = QKV + 2 * H + h * HD;

    {
        uint4 z = make_uint4(0, 0, 0, 0);
        for (int i = tid; i < AQT * QKP / 8; i += 128) ((uint4*)&Qs[0][0])[i] = z;
        for (int i = tid; i < AKT * QKP / 8; i += 128) ((uint4*)&Ks[0][0])[i] = z;
        for (int i = tid; i < HD * VTP / 8; i += 128) ((uint4*)&Vt[0][0])[i] = z;
    }
    __syncthreads();

    for (int i = tid; i < AQT * 9; i += 128) {
        int r = i / 9, c = i - r * 9;
        *(uint4*)&Qs[r][c * 8] = *(const uint4*)&Q[(size_t)(q0 + r) * QKVN + c * 8];
    }

    int rs0[2], rs1[2];
    rs0[0] = segs[q0 + warp * 16 + fr];     rs1[0] = sege[q0 + warp * 16 + fr];
    rs0[1] = segs[q0 + warp * 16 + fr + 8]; rs1[1] = sege[q0 + warp * 16 + fr + 8];
    float m[2] = {-3.0e38f, -3.0e38f};
    float l[2] = {0.f, 0.f};
    float out[9][4];
#pragma unroll
    for (int nt = 0; nt < 9; ++nt)
#pragma unroll
        for (int i = 0; i < 4; ++i) out[nt][i] = 0.f;

    int kstart = segs[q0];
    int kend = sege[q0 + AQT - 1];

    for (int c0 = kstart; c0 < kend; c0 += AKT) {
        int len = min(AKT, kend - c0);
        __syncthreads();

        for (int i = tid; i < len * 9; i += 128) {
            int r = i / 9, c = i - r * 9;
            *(uint4*)&Ks[r][c * 8] = *(const uint4*)&K[(size_t)(c0 + r) * QKVN + c * 8];
        }
        for (int i = tid; i < len * HD; i += 128) {
            int r = i / HD, d = i - r * HD;
            Vt[d][r] = V[(size_t)(c0 + r) * QKVN + d];
        }
        __syncthreads();

        float sc[8][4];
#pragma unroll
        for (int nt = 0; nt < 8; ++nt)
#pragma unroll
            for (int i = 0; i < 4; ++i) sc[nt][i] = 0.f;

#pragma unroll
        for (int kk = 0; kk < 5; ++kk) {
            int kb = kk * 16;
            uint32_t a[4];
            a[0] = *(const uint32_t*)&Qs[warp * 16 + fr][kb + fc * 2];
            a[1] = *(const uint32_t*)&Qs[warp * 16 + fr + 8][kb + fc * 2];
            a[2] = *(const uint32_t*)&Qs[warp * 16 + fr][kb + fc * 2 + 8];
            a[3] = *(const uint32_t*)&Qs[warp * 16 + fr + 8][kb + fc * 2 + 8];
#pragma unroll
            for (int nt = 0; nt < 8; ++nt) {
                uint32_t b[2];
                b[0] = *(const uint32_t*)&Ks[nt * 8 + fr][kb + fc * 2];
                b[1] = *(const uint32_t*)&Ks[nt * 8 + fr][kb + fc * 2 + 8];
                mma_f16(sc[nt], a, b);
            }
        }

        float mx0 = -3.0e38f, mx1 = -3.0e38f;
#pragma unroll
        for (int nt = 0; nt < 8; ++nt) {
            int kg0 = c0 + nt * 8 + fc * 2;
            int kg1 = kg0 + 1;
            sc[nt][0] = (kg0 >= rs0[0] && kg0 < rs1[0]) ? sc[nt][0] * scale : -3.0e38f;
            sc[nt][1] = (kg1 >= rs0[0] && kg1 < rs1[0]) ? sc[nt][1] * scale : -3.0e38f;
            sc[nt][2] = (kg0 >= rs0[1] && kg0 < rs1[1]) ? sc[nt][2] * scale : -3.0e38f;
            sc[nt][3] = (kg1 >= rs0[1] && kg1 < rs1[1]) ? sc[nt][3] * scale : -3.0e38f;
            mx0 = fmaxf(mx0, fmaxf(sc[nt][0], sc[nt][1]));
            mx1 = fmaxf(mx1, fmaxf(sc[nt][2], sc[nt][3]));
        }
#pragma unroll
        for (int ofs = 1; ofs <= 2; ofs <<= 1) {
            mx0 = fmaxf(mx0, __shfl_xor_sync(0xffffffffu, mx0, ofs));
            mx1 = fmaxf(mx1, __shfl_xor_sync(0xffffffffu, mx1, ofs));
        }
        float mnew0 = fmaxf(m[0], mx0);
        float mnew1 = fmaxf(m[1], mx1);
        float corr0 = __expf(m[0] - mnew0);
        float corr1 = __expf(m[1] - mnew1);

        float ps0 = 0.f, ps1 = 0.f;
#pragma unroll
        for (int nt = 0; nt < 8; ++nt) {
            sc[nt][0] = (sc[nt][0] > -1.0e38f) ? __expf(sc[nt][0] - mnew0) : 0.f;
            sc[nt][1] = (sc[nt][1] > -1.0e38f) ? __expf(sc[nt][1] - mnew0) : 0.f;
            sc[nt][2] = (sc[nt][2] > -1.0e38f) ? __expf(sc[nt][2] - mnew1) : 0.f;
            sc[nt][3] = (sc[nt][3] > -1.0e38f) ? __expf(sc[nt][3] - mnew1) : 0.f;
            ps0 += sc[nt][0] + sc[nt][1];
            ps1 += sc[nt][2] + sc[nt][3];
        }
#pragma unroll
        for (int ofs = 1; ofs <= 2; ofs <<= 1) {
            ps0 += __shfl_xor_sync(0xffffffffu, ps0, ofs);
            ps1 += __shfl_xor_sync(0xffffffffu, ps1, ofs);
        }
        l[0] = l[0] * corr0 + ps0;
        l[1] = l[1] * corr1 + ps1;
        m[0] = mnew0;
        m[1] = mnew1;

#pragma unroll
        for (int nt = 0; nt < 9; ++nt) {
            out[nt][0] *= corr0; out[nt][1] *= corr0;
            out[nt][2] *= corr1; out[nt][3] *= corr1;
        }
        uint32_t pr0[8], pr1[8];
#pragma unroll
        for (int nt = 0; nt < 8; ++nt) {
            __half2 h0 = __floats2half2_rn(sc[nt][0], sc[nt][1]);
            __half2 h1 = __floats2half2_rn(sc[nt][2], sc[nt][3]);
            pr0[nt] = *(uint32_t*)&h0;
            pr1[nt] = *(uint32_t*)&h1;
        }
#pragma unroll
        for (int j = 0; j < 4; ++j) {
            uint32_t a[4] = {pr0[2 * j], pr1[2 * j], pr0[2 * j + 1], pr1[2 * j + 1]};
            int kb = j * 16;
#pragma unroll
            for (int nt = 0; nt < 9; ++nt) {
                uint32_t b[2];
                b[0] = *(const uint32_t*)&Vt[nt * 8 + fr][kb + fc * 2];
                b[1] = *(const uint32_t*)&Vt[nt * 8 + fr][kb + fc * 2 + 8];
                mma_f16(out[nt], a, b);
            }
        }
    }

    float inv0 = 1.f / l[0];
    float inv1 = 1.f / l[1];
    size_t base0 = (size_t)(q0 + warp * 16 + fr) * H + h * HD;
    size_t base1 = (size_t)(q0 + warp * 16 + fr + 8) * H + h * HD;
#pragma unroll
    for (int nt = 0; nt < 9; ++nt) {
        int col = nt * 8 + fc * 2;
        __half2 o0 = __floats2half2_rn(out[nt][0] * inv0, out[nt][1] * inv0);
        __half2 o1 = __floats2half2_rn(out[nt][2] * inv1, out[nt][3] * inv1);
        *(__half2*)&O[base0 + col] = o0;
        *(__half2*)&O[base1 + col] = o1;
    }
}

// ---------------- launch ----------------
extern "C" void kernel_launch(void* const* d_in, const int* in_sizes, int n_in,
                              void* d_out, int out_size) {
    const float* hs    = (const float*)d_in[0];
    const int*   doc   = (const int*)d_in[1];
    const float* q_w   = (const float*)d_in[2];
    const float* q_b   = (const float*)d_in[3];
    const float* k_w   = (const float*)d_in[4];
    const float* k_b   = (const float*)d_in[5];
    const float* v_w   = (const float*)d_in[6];
    const float* v_b   = (const float*)d_in[7];
    const float* o_w   = (const float*)d_in[8];
    const float* o_b   = (const float*)d_in[9];
    const float* ln1_g = (const float*)d_in[10];
    const float* ln1_b = (const float*)d_in[11];
    const float* ln2_g = (const float*)d_in[12];
    const float* ln2_b = (const float*)d_in[13];
    const float* fc1_w = (const float*)d_in[14];
    const float* fc1_b = (const float*)d_in[15];
    const float* fc2_w = (const float*)d_in[16];
    const float* fc2_b = (const float*)d_in[17];
    float* out = (float*)d_out;

    __half *xnh, *qkvh, *attnh, *yh, *ffh;
    __half *wqkvh, *owh, *fc1h, *fc2h;
    float *hid, *bqkv;
    int *segs, *sege;
    cudaGetSymbolAddress((void**)&xnh,   g_xnh);
    cudaGetSymbolAddress((void**)&qkvh,  g_qkvh);
    cudaGetSymbolAddress((void**)&attnh, g_attnh);
    cudaGetSymbolAddress((void**)&hid,   g_hid);
    cudaGetSymbolAddress((void**)&yh,    g_yh);
    cudaGetSymbolAddress((void**)&ffh,   g_ffh);
    cudaGetSymbolAddress((void**)&wqkvh, g_wqkvh);
    cudaGetSymbolAddress((void**)&owh,   g_owh);
    cudaGetSymbolAddress((void**)&fc1h,  g_fc1h);
    cudaGetSymbolAddress((void**)&fc2h,  g_fc2h);
    cudaGetSymbolAddress((void**)&bqkv,  g_bqkv);
    cudaGetSymbolAddress((void**)&segs,  g_segs);
    cudaGetSymbolAddress((void**)&sege,  g_sege);

    int nHH4 = H * H / 4;
    int nHF4 = H * FF / 4;
    // q/k/v weights packed contiguously into wqkvh rows [0,H),[H,2H),[2H,3H)
    cvt_f2h4<<<dim3((nHH4 + 255) / 256, 4), 256>>>(
        (const float4*)q_w, (const float4*)k_w, (const float4*)v_w, (const float4*)o_w,
        (__half2*)wqkvh, (__half2*)(wqkvh + (size_t)H * H),
        (__half2*)(wqkvh + (size_t)2 * H * H), (__half2*)owh, nHH4);
    cvt_f2h<<<(nHF4 + 255) / 256, 256>>>((const float4*)fc1_w, (__half2*)fc1h, nHF4);
    cvt_f2h<<<(nHF4 + 255) / 256, 256>>>((const float4*)fc2_w, (__half2*)fc2h, nHF4);
    pack_bias<<<(H + 255) / 256, 256>>>(q_b, k_b, v_b, bqkv);

    dim3 gQKV(QKVN / BN, S / BM);            // (27, 32)
    dim3 gH(H / BN, S / BM);                 // (9, 32)
    dim3 gF((FF + BN - 1) / BN, S / BM);     // (34, 32)

    ln_kernel_h<<<S, 256>>>(hs, ln1_g, ln1_b, xnh);
    doc_ranges<<<(S + 255) / 256, 256>>>(doc, segs, sege);

    gemm_f16<<<gQKV, 256>>>(xnh, wqkvh, bqkv, nullptr, nullptr, qkvh, S, QKVN, H, 0);

    attn_mma<<<dim3(S / AQT, NH), 128>>>(qkvh, segs, sege, attnh);

    gemm_f16<<<gH, 256>>>(attnh, owh, o_b, hs, hid, nullptr, S, H, H, 2);

    ln_kernel_h<<<S, 256>>>(hid, ln2_g, ln2_b, yh);

    gemm_f16<<<gF, 256>>>(yh, fc1h, fc1_b, nullptr, nullptr, ffh, S, FF, H, 1);
    gemm_f16<<<gH, 256>>>(ffh, fc2h, fc2_b, hid, out, nullptr, S, H, FF, 2);
}

// round 13
// speedup vs baseline: 8.9394x; 1.0580x over previous
#include <cuda_runtime.h>
#include <cuda_fp16.h>
#include <math.h>
#include <stdint.h>

#define S 4096
#define H 1152
#define NH 16
#define HD 72
#define FF 4304
#define QKVN (3 * H)          // 3456
#define LN_EPS 1e-6f

// ---------------- scratch (allocation-free: device globals) ----------------
__device__ __half g_xnh[S * H];
__device__ __half g_qkvh[(size_t)S * QKVN];
__device__ __half g_attnh[S * H];
__device__ float  g_hid[S * H];
__device__ __half g_yh[S * H];
__device__ __half g_ffh[(size_t)S * FF];
__device__ __half g_wqkvh[(size_t)QKVN * H];
__device__ __half g_owh[H * H];
__device__ __half g_fc1h[(size_t)H * FF];
__device__ __half g_fc2h[(size_t)H * FF];
__device__ float  g_bqkv[QKVN];
__device__ int g_segs[S];
__device__ int g_sege[S];

// ---------------- weight conversion: float -> half ----------------
__global__ __launch_bounds__(256) void cvt_f2h(const float4* __restrict__ x,
                                               __half2* __restrict__ y, int n4) {
    int i = blockIdx.x * blockDim.x + threadIdx.x;
    if (i < n4) {
        float4 v = x[i];
        y[2 * i]     = __floats2half2_rn(v.x, v.y);
        y[2 * i + 1] = __floats2half2_rn(v.z, v.w);
    }
}

// 4 same-size tensors in one launch (blockIdx.y selects)
__global__ __launch_bounds__(256) void cvt_f2h4(const float4* __restrict__ x0,
                                                const float4* __restrict__ x1,
                                                const float4* __restrict__ x2,
                                                const float4* __restrict__ x3,
                                                __half2* __restrict__ y0,
                                                __half2* __restrict__ y1,
                                                __half2* __restrict__ y2,
                                                __half2* __restrict__ y3,
                                                int n4) {
    int i = blockIdx.x * blockDim.x + threadIdx.x;
    if (i >= n4) return;
    const float4* x; __half2* y;
    switch (blockIdx.y) {
        case 0: x = x0; y = y0; break;
        case 1: x = x1; y = y1; break;
        case 2: x = x2; y = y2; break;
        default: x = x3; y = y3; break;
    }
    float4 v = x[i];
    y[2 * i]     = __floats2half2_rn(v.x, v.y);
    y[2 * i + 1] = __floats2half2_rn(v.z, v.w);
}

__global__ __launch_bounds__(256) void pack_bias(const float* __restrict__ qb,
                                                 const float* __restrict__ kb,
                                                 const float* __restrict__ vb,
                                                 float* __restrict__ dst) {
    int i = blockIdx.x * blockDim.x + threadIdx.x;
    if (i < H) {
        dst[i] = qb[i];
        dst[H + i] = kb[i];
        dst[2 * H + i] = vb[i];
    }
}

// ---------------- LayerNorm: one block per row, half output ----------------
__global__ __launch_bounds__(256) void ln_kernel_h(const float* __restrict__ x,
                                                   const float* __restrict__ g,
                                                   const float* __restrict__ b,
                                                   __half* __restrict__ y) {
    int row = blockIdx.x;
    const float* xr = x + (size_t)row * H;
    __shared__ float red[256];
    int tid = threadIdx.x;

    float s = 0.f;
    for (int i = tid; i < H; i += 256) s += xr[i];
    red[tid] = s;
    __syncthreads();
    for (int off = 128; off > 0; off >>= 1) {
        if (tid < off) red[tid] += red[tid + off];
        __syncthreads();
    }
    float mu = red[0] * (1.0f / H);
    __syncthreads();

    float sq = 0.f;
    for (int i = tid; i < H; i += 256) {
        float d = xr[i] - mu;
        sq += d * d;
    }
    red[tid] = sq;
    __syncthreads();
    for (int off = 128; off > 0; off >>= 1) {
        if (tid < off) red[tid] += red[tid + off];
        __syncthreads();
    }
    float inv = rsqrtf(red[0] * (1.0f / H) + LN_EPS);

    __half* yr = y + (size_t)row * H;
    for (int i = tid; i < H; i += 256)
        yr[i] = __float2half((xr[i] - mu) * inv * g[i] + b[i]);
}

// ---------------- document segment ranges (ids are sorted) ----------------
__global__ void doc_ranges(const int* __restrict__ ids, int* __restrict__ segs,
                           int* __restrict__ sege) {
    int i = blockIdx.x * blockDim.x + threadIdx.x;
    if (i >= S) return;
    int d = ids[i];
    int lo = 0, hi = S;
    while (lo < hi) { int mid = (lo + hi) >> 1; if (ids[mid] < d) lo = mid + 1; else hi = mid; }
    segs[i] = lo;
    lo = 0; hi = S;
    while (lo < hi) { int mid = (lo + hi) >> 1; if (ids[mid] <= d) lo = mid + 1; else hi = mid; }
    sege[i] = lo;
}

// ---------------- common mma / ldmatrix ----------------
__device__ __forceinline__ void mma_f16(float* c, const uint32_t* a, const uint32_t* b) {
    asm volatile(
        "mma.sync.aligned.m16n8k16.row.col.f32.f16.f16.f32 "
        "{%0,%1,%2,%3}, {%4,%5,%6,%7}, {%8,%9}, {%0,%1,%2,%3};"
        : "+f"(c[0]), "+f"(c[1]), "+f"(c[2]), "+f"(c[3])
        : "r"(a[0]), "r"(a[1]), "r"(a[2]), "r"(a[3]), "r"(b[0]), "r"(b[1]));
}

__device__ __forceinline__ void ldm_x4(uint32_t* r, uint32_t addr) {
    asm volatile("ldmatrix.sync.aligned.m8n8.x4.shared.b16 {%0,%1,%2,%3}, [%4];"
                 : "=r"(r[0]), "=r"(r[1]), "=r"(r[2]), "=r"(r[3]) : "r"(addr));
}
__device__ __forceinline__ void ldm_x2(uint32_t* r, uint32_t addr) {
    asm volatile("ldmatrix.sync.aligned.m8n8.x2.shared.b16 {%0,%1}, [%2];"
                 : "=r"(r[0]), "=r"(r[1]) : "r"(addr));
}

// ---------------- FP16 tensor-core GEMM (ldmatrix fragments) ---------------
#define BM 128
#define BN 128
#define BKH 32
#define PITCH 40

__device__ __forceinline__ void cp16(void* dst, const void* src, bool valid,
                                     const void* safe) {
    uint32_t d = (uint32_t)__cvta_generic_to_shared(dst);
    const void* s = valid ? src : safe;   // always in-bounds address
    int sz = valid ? 16 : 0;
    asm volatile("cp.async.cg.shared.global [%0], [%1], 16, %2;\n"
                 :: "r"(d), "l"(s), "r"(sz));
}

__global__ __launch_bounds__(256, 2) void gemm_f16(const __half* __restrict__ A,
                                                   const __half* __restrict__ W,
                                                   const float* __restrict__ bias,
                                                   const float* __restrict__ res,
                                                   float* __restrict__ C,
                                                   __half* __restrict__ Ch,
                                                   int M, int N, int K, int epi) {
    __shared__ __half As[2][BM][PITCH];
    __shared__ __half Ws[2][BN][PITCH];

    int tid = threadIdx.x;
    int lane = tid & 31, warp = tid >> 5;
    int wn = warp & 3;
    int wm = warp >> 2;
    int m0 = blockIdx.y * BM;
    int n0 = blockIdx.x * BN;

    int lr = tid >> 1;
    int lc = (tid & 1) * 2;

    const __half* Ab = A + (size_t)m0 * K;

    float acc[4][4][4];
#pragma unroll
    for (int i = 0; i < 4; ++i)
#pragma unroll
        for (int j = 0; j < 4; ++j)
#pragma unroll
            for (int l = 0; l < 4; ++l) acc[i][j][l] = 0.f;

    int nk = (K + BKH - 1) / BKH;

    {
#pragma unroll
        for (int cc = 0; cc < 2; ++cc) {
            int c = lc + cc;
            cp16(&As[0][lr][c * 8], Ab + (size_t)lr * K + c * 8,
                 (c * 8 + 8 <= K), A);
            cp16(&Ws[0][lr][c * 8], W + (size_t)(n0 + lr) * K + c * 8,
                 ((n0 + lr) < N) && (c * 8 + 8 <= K), W);
        }
    }
    asm volatile("cp.async.commit_group;\n" ::: "memory");

    uint32_t aRowOff = (uint32_t)((wm * 64 + (lane & 15)) * PITCH + ((lane >> 4) << 3)) * 2;
    uint32_t bRowOff = (uint32_t)((wn * 32 + (lane & 7)) * PITCH + (((lane >> 3) & 1) << 3)) * 2;

    int fr = lane >> 2;
    int fc = lane & 3;

    for (int t = 0; t < nk; ++t) {
        asm volatile("cp.async.wait_group 0;\n" ::: "memory");
        __syncthreads();

        int st = t & 1;
        if (t + 1 < nk) {
            int ko = (t + 1) * BKH;
#pragma unroll
            for (int cc = 0; cc < 2; ++cc) {
                int c = lc + cc;
                cp16(&As[st ^ 1][lr][c * 8], Ab + (size_t)lr * K + ko + c * 8,
                     (ko + c * 8 + 8 <= K), A);
                cp16(&Ws[st ^ 1][lr][c * 8], W + (size_t)(n0 + lr) * K + ko + c * 8,
                     ((n0 + lr) < N) && (ko + c * 8 + 8 <= K), W);
            }
        }
        asm volatile("cp.async.commit_group;\n" ::: "memory");

        uint32_t aSm = (uint32_t)__cvta_generic_to_shared(&As[st][0][0]) + aRowOff;
        uint32_t bSm = (uint32_t)__cvta_generic_to_shared(&Ws[st][0][0]) + bRowOff;

#pragma unroll
        for (int kk = 0; kk < 2; ++kk) {
            uint32_t kB = (uint32_t)(kk * 16 * 2);
            uint32_t a[4][4], b[4][2];
#pragma unroll
            for (int mt = 0; mt < 4; ++mt)
                ldm_x4(a[mt], aSm + kB + (uint32_t)(mt * 16 * PITCH * 2));
#pragma unroll
            for (int nt = 0; nt < 4; ++nt)
                ldm_x2(b[nt], bSm + kB + (uint32_t)(nt * 8 * PITCH * 2));
#pragma unroll
            for (int mt = 0; mt < 4; ++mt)
#pragma unroll
                for (int nt = 0; nt < 4; ++nt)
                    mma_f16(acc[mt][nt], a[mt], b[nt]);
        }
    }

    // epilogue: column-pair vectorized stores (half2 / float2)
#pragma unroll
    for (int mt = 0; mt < 4; ++mt) {
        int row = m0 + wm * 64 + mt * 16 + fr;
#pragma unroll
        for (int nt = 0; nt < 4; ++nt) {
            int col = n0 + wn * 32 + nt * 8 + fc * 2;
            if (col >= N) continue;           // N even, col even -> col+1 < N too
            float b0 = bias[col];
            float b1 = bias[col + 1];
#pragma unroll
            for (int hh = 0; hh < 2; ++hh) {
                int r = row + (hh ? 8 : 0);
                float v0 = acc[mt][nt][hh * 2 + 0] + b0;
                float v1 = acc[mt][nt][hh * 2 + 1] + b1;
                if (epi == 1) {
                    float u0 = 0.7978845608028654f * (v0 + 0.044715f * v0 * v0 * v0);
                    float e0 = __expf(2.f * u0);
                    v0 = 0.5f * v0 * (2.f - 2.f / (e0 + 1.f));
                    float u1 = 0.7978845608028654f * (v1 + 0.044715f * v1 * v1 * v1);
                    float e1 = __expf(2.f * u1);
                    v1 = 0.5f * v1 * (2.f - 2.f / (e1 + 1.f));
                } else if (epi == 2) {
                    float2 rv = *(const float2*)&res[(size_t)r * N + col];
                    v0 += rv.x;
                    v1 += rv.y;
                }
                if (Ch) {
                    __half2 hv = __floats2half2_rn(v0, v1);
                    *(__half2*)&Ch[(size_t)r * N + col] = hv;
                } else {
                    float2 fv;
                    fv.x = v0; fv.y = v1;
                    *(float2*)&C[(size_t)r * N + col] = fv;
                }
            }
        }
    }
}

// ---------------- tensor-core flash attention (doc-masked) -----------------
#define AQT 64
#define AKT 64
#define QKP 88
#define VTP 72

__global__ __launch_bounds__(128) void attn_mma(const __half* __restrict__ QKV,
                                                const int* __restrict__ segs,
                                                const int* __restrict__ sege,
                                                __half* __restrict__ O) {
    __shared__ __half Qs[AQT][QKP];
    __shared__ __half Ks[AKT][QKP];
    __shared__ __half Vt[HD][VTP];

    int h = blockIdx.y;
    int q0 = blockIdx.x * AQT;
    int tid = threadIdx.x, lane = tid & 31, warp = tid >> 5;
    int fr = lane >> 2, fc = lane & 3;
    const float scale = 0.11785113019775793f;

    const __half* Q = QKV + h * HD;
    const __half* K = QKV + H + h * HD;
    const __half* V = QKV + 2 * H + h * HD;

    {
        uint4 z = make_uint4(0, 0, 0, 0);
        for (int i = tid; i < AQT * QKP / 8; i += 128) ((uint4*)&Qs[0][0])[i] = z;
        for (int i = tid; i < AKT * QKP / 8; i += 128) ((uint4*)&Ks[0][0])[i] = z;
        for (int i = tid; i < HD * VTP / 8; i += 128) ((uint4*)&Vt[0][0])[i] = z;
    }
    __syncthreads();

    for (int i = tid; i < AQT * 9; i += 128) {
        int r = i / 9, c = i - r * 9;
        *(uint4*)&Qs[r][c * 8] = *(const uint4*)&Q[(size_t)(q0 + r) * QKVN + c * 8];
    }

    int rs0[2], rs1[2];
    rs0[0] = segs[q0 + warp * 16 + fr];     rs1[0] = sege[q0 + warp * 16 + fr];
    rs0[1] = segs[q0 + warp * 16 + fr + 8]; rs1[1] = sege[q0 + warp * 16 + fr + 8];
    float m[2] = {-3.0e38f, -3.0e38f};
    float l[2] = {0.f, 0.f};
    float out[9][4];
#pragma unroll
    for (int nt = 0; nt < 9; ++nt)
#pragma unroll
        for (int i = 0; i < 4; ++i) out[nt][i] = 0.f;

    int kstart = segs[q0];
    int kend = sege[q0 + AQT - 1];

    for (int c0 = kstart; c0 < kend; c0 += AKT) {
        int len = min(AKT, kend - c0);
        __syncthreads();

        for (int i = tid; i < len * 9; i += 128) {
            int r = i / 9, c = i - r * 9;
            *(uint4*)&Ks[r][c * 8] = *(const uint4*)&K[(size_t)(c0 + r) * QKVN + c * 8];
        }
        for (int i = tid; i < len * HD; i += 128) {
            int r = i / HD, d = i - r * HD;
            Vt[d][r] = V[(size_t)(c0 + r) * QKVN + d];
        }
        __syncthreads();

        float sc[8][4];
#pragma unroll
        for (int nt = 0; nt < 8; ++nt)
#pragma unroll
            for (int i = 0; i < 4; ++i) sc[nt][i] = 0.f;

#pragma unroll
        for (int kk = 0; kk < 5; ++kk) {
            int kb = kk * 16;
            uint32_t a[4];
            a[0] = *(const uint32_t*)&Qs[warp * 16 + fr][kb + fc * 2];
            a[1] = *(const uint32_t*)&Qs[warp * 16 + fr + 8][kb + fc * 2];
            a[2] = *(const uint32_t*)&Qs[warp * 16 + fr][kb + fc * 2 + 8];
            a[3] = *(const uint32_t*)&Qs[warp * 16 + fr + 8][kb + fc * 2 + 8];
#pragma unroll
            for (int nt = 0; nt < 8; ++nt) {
                uint32_t b[2];
                b[0] = *(const uint32_t*)&Ks[nt * 8 + fr][kb + fc * 2];
                b[1] = *(const uint32_t*)&Ks[nt * 8 + fr][kb + fc * 2 + 8];
                mma_f16(sc[nt], a, b);
            }
        }

        float mx0 = -3.0e38f, mx1 = -3.0e38f;
#pragma unroll
        for (int nt = 0; nt < 8; ++nt) {
            int kg0 = c0 + nt * 8 + fc * 2;
            int kg1 = kg0 + 1;
            sc[nt][0] = (kg0 >= rs0[0] && kg0 < rs1[0]) ? sc[nt][0] * scale : -3.0e38f;
            sc[nt][1] = (kg1 >= rs0[0] && kg1 < rs1[0]) ? sc[nt][1] * scale : -3.0e38f;
            sc[nt][2] = (kg0 >= rs0[1] && kg0 < rs1[1]) ? sc[nt][2] * scale : -3.0e38f;
            sc[nt][3] = (kg1 >= rs0[1] && kg1 < rs1[1]) ? sc[nt][3] * scale : -3.0e38f;
            mx0 = fmaxf(mx0, fmaxf(sc[nt][0], sc[nt][1]));
            mx1 = fmaxf(mx1, fmaxf(sc[nt][2], sc[nt][3]));
        }
#pragma unroll
        for (int ofs = 1; ofs <= 2; ofs <<= 1) {
            mx0 = fmaxf(mx0, __shfl_xor_sync(0xffffffffu, mx0, ofs));
            mx1 = fmaxf(mx1, __shfl_xor_sync(0xffffffffu, mx1, ofs));
        }
        float mnew0 = fmaxf(m[0], mx0);
        float mnew1 = fmaxf(m[1], mx1);
        float corr0 = __expf(m[0] - mnew0);
        float corr1 = __expf(m[1] - mnew1);

        float ps0 = 0.f, ps1 = 0.f;
#pragma unroll
        for (int nt = 0; nt < 8; ++nt) {
            sc[nt][0] = (sc[nt][0] > -1.0e38f) ? __expf(sc[nt][0] - mnew0) : 0.f;
            sc[nt][1] = (sc[nt][1] > -1.0e38f) ? __expf(sc[nt][1] - mnew0) : 0.f;
            sc[nt][2] = (sc[nt][2] > -1.0e38f) ? __expf(sc[nt][2] - mnew1) : 0.f;
            sc[nt][3] = (sc[nt][3] > -1.0e38f) ? __expf(sc[nt][3] - mnew1) : 0.f;
            ps0 += sc[nt][0] + sc[nt][1];
            ps1 += sc[nt][2] + sc[nt][3];
        }
#pragma unroll
        for (int ofs = 1; ofs <= 2; ofs <<= 1) {
            ps0 += __shfl_xor_sync(0xffffffffu, ps0, ofs);
            ps1 += __shfl_xor_sync(0xffffffffu, ps1, ofs);
        }
        l[0] = l[0] * corr0 + ps0;
        l[1] = l[1] * corr1 + ps1;
        m[0] = mnew0;
        m[1] = mnew1;

#pragma unroll
        for (int nt = 0; nt < 9; ++nt) {
            out[nt][0] *= corr0; out[nt][1] *= corr0;
            out[nt][2] *= corr1; out[nt][3] *= corr1;
        }
        uint32_t pr0[8], pr1[8];
#pragma unroll
        for (int nt = 0; nt < 8; ++nt) {
            __half2 h0 = __floats2half2_rn(sc[nt][0], sc[nt][1]);
            __half2 h1 = __floats2half2_rn(sc[nt][2], sc[nt][3]);
            pr0[nt] = *(uint32_t*)&h0;
            pr1[nt] = *(uint32_t*)&h1;
        }
#pragma unroll
        for (int j = 0; j < 4; ++j) {
            uint32_t a[4] = {pr0[2 * j], pr1[2 * j], pr0[2 * j + 1], pr1[2 * j + 1]};
            int kb = j * 16;
#pragma unroll
            for (int nt = 0; nt < 9; ++nt) {
                uint32_t b[2];
                b[0] = *(const uint32_t*)&Vt[nt * 8 + fr][kb + fc * 2];
                b[1] = *(const uint32_t*)&Vt[nt * 8 + fr][kb + fc * 2 + 8];
                mma_f16(out[nt], a, b);
            }
        }
    }

    float inv0 = 1.f / l[0];
    float inv1 = 1.f / l[1];
    size_t base0 = (size_t)(q0 + warp * 16 + fr) * H + h * HD;
    size_t base1 = (size_t)(q0 + warp * 16 + fr + 8) * H + h * HD;
#pragma unroll
    for (int nt = 0; nt < 9; ++nt) {
        int col = nt * 8 + fc * 2;
        __half2 o0 = __floats2half2_rn(out[nt][0] * inv0, out[nt][1] * inv0);
        __half2 o1 = __floats2half2_rn(out[nt][2] * inv1, out[nt][3] * inv1);
        *(__half2*)&O[base0 + col] = o0;
        *(__half2*)&O[base1 + col] = o1;
    }
}

// ---------------- launch ----------------
extern "C" void kernel_launch(void* const* d_in, const int* in_sizes, int n_in,
                              void* d_out, int out_size) {
    const float* hs    = (const float*)d_in[0];
    const int*   doc   = (const int*)d_in[1];
    const float* q_w   = (const float*)d_in[2];
    const float* q_b   = (const float*)d_in[3];
    const float* k_w   = (const float*)d_in[4];
    const float* k_b   = (const float*)d_in[5];
    const float* v_w   = (const float*)d_in[6];
    const float* v_b   = (const float*)d_in[7];
    const float* o_w   = (const float*)d_in[8];
    const float* o_b   = (const float*)d_in[9];
    const float* ln1_g = (const float*)d_in[10];
    const float* ln1_b = (const float*)d_in[11];
    const float* ln2_g = (const float*)d_in[12];
    const float* ln2_b = (const float*)d_in[13];
    const float* fc1_w = (const float*)d_in[14];
    const float* fc1_b = (const float*)d_in[15];
    const float* fc2_w = (const float*)d_in[16];
    const float* fc2_b = (const float*)d_in[17];
    float* out = (float*)d_out;

    __half *xnh, *qkvh, *attnh, *yh, *ffh;
    __half *wqkvh, *owh, *fc1h, *fc2h;
    float *hid, *bqkv;
    int *segs, *sege;
    cudaGetSymbolAddress((void**)&xnh,   g_xnh);
    cudaGetSymbolAddress((void**)&qkvh,  g_qkvh);
    cudaGetSymbolAddress((void**)&attnh, g_attnh);
    cudaGetSymbolAddress((void**)&hid,   g_hid);
    cudaGetSymbolAddress((void**)&yh,    g_yh);
    cudaGetSymbolAddress((void**)&ffh,   g_ffh);
    cudaGetSymbolAddress((void**)&wqkvh, g_wqkvh);
    cudaGetSymbolAddress((void**)&owh,   g_owh);
    cudaGetSymbolAddress((void**)&fc1h,  g_fc1h);
    cudaGetSymbolAddress((void**)&fc2h,  g_fc2h);
    cudaGetSymbolAddress((void**)&bqkv,  g_bqkv);
    cudaGetSymbolAddress((void**)&segs,  g_segs);
    cudaGetSymbolAddress((void**)&sege,  g_sege);

    int nHH4 = H * H / 4;
    int nHF4 = H * FF / 4;
    cvt_f2h4<<<dim3((nHH4 + 255) / 256, 4), 256>>>(
        (const float4*)q_w, (const float4*)k_w, (const float4*)v_w, (const float4*)o_w,
        (__half2*)wqkvh, (__half2*)(wqkvh + (size_t)H * H),
        (__half2*)(wqkvh + (size_t)2 * H * H), (__half2*)owh, nHH4);
    cvt_f2h<<<(nHF4 + 255) / 256, 256>>>((const float4*)fc1_w, (__half2*)fc1h, nHF4);
    cvt_f2h<<<(nHF4 + 255) / 256, 256>>>((const float4*)fc2_w, (__half2*)fc2h, nHF4);
    pack_bias<<<(H + 255) / 256, 256>>>(q_b, k_b, v_b, bqkv);

    dim3 gQKV(QKVN / BN, S / BM);            // (27, 32)
    dim3 gH(H / BN, S / BM);                 // (9, 32)
    dim3 gF((FF + BN - 1) / BN, S / BM);     // (34, 32)

    ln_kernel_h<<<S, 256>>>(hs, ln1_g, ln1_b, xnh);
    doc_ranges<<<(S + 255) / 256, 256>>>(doc, segs, sege);

    gemm_f16<<<gQKV, 256>>>(xnh, wqkvh, bqkv, nullptr, nullptr, qkvh, S, QKVN, H, 0);

    attn_mma<<<dim3(S / AQT, NH), 128>>>(qkvh, segs, sege, attnh);

    gemm_f16<<<gH, 256>>>(attnh, owh, o_b, hs, hid, nullptr, S, H, H, 2);

    ln_kernel_h<<<S, 256>>>(hid, ln2_g, ln2_b, yh);

    gemm_f16<<<gF, 256>>>(yh, fc1h, fc1_b, nullptr, nullptr, ffh, S, FF, H, 1);
    gemm_f16<<<gH, 256>>>(ffh, fc2h, fc2_b, hid, out, nullptr, S, H, FF, 2);
}

// round 15
// speedup vs baseline: 9.2422x; 1.0339x over previous
#include <cuda_runtime.h>
#include <cuda_fp16.h>
#include <math.h>
#include <stdint.h>

#define S 4096
#define H 1152
#define NH 16
#define HD 72
#define FF 4304
#define QKVN (3 * H)          // 3456
#define LN_EPS 1e-6f

// ---------------- scratch (allocation-free: device globals) ----------------
__device__ __half g_xnh[S * H];
__device__ __half g_qkvh[(size_t)S * QKVN];
__device__ __half g_attnh[S * H];
__device__ float  g_hid[S * H];
__device__ __half g_yh[S * H];
__device__ __half g_ffh[(size_t)S * FF];
__device__ __half g_wqkvh[(size_t)QKVN * H];
__device__ __half g_owh[H * H];
__device__ __half g_fc1h[(size_t)H * FF];
__device__ __half g_fc2h[(size_t)H * FF];
__device__ float  g_bqkv[QKVN];
__device__ int g_segs[S];
__device__ int g_sege[S];

// ---------------- weight conversion: float -> half ----------------
__global__ __launch_bounds__(256) void cvt_f2h(const float4* __restrict__ x,
                                               __half2* __restrict__ y, int n4) {
    int i = blockIdx.x * blockDim.x + threadIdx.x;
    if (i < n4) {
        float4 v = x[i];
        y[2 * i]     = __floats2half2_rn(v.x, v.y);
        y[2 * i + 1] = __floats2half2_rn(v.z, v.w);
    }
}

// 4 same-size tensors in one launch (blockIdx.y selects)
__global__ __launch_bounds__(256) void cvt_f2h4(const float4* __restrict__ x0,
                                                const float4* __restrict__ x1,
                                                const float4* __restrict__ x2,
                                                const float4* __restrict__ x3,
                                                __half2* __restrict__ y0,
                                                __half2* __restrict__ y1,
                                                __half2* __restrict__ y2,
                                                __half2* __restrict__ y3,
                                                int n4) {
    int i = blockIdx.x * blockDim.x + threadIdx.x;
    if (i >= n4) return;
    const float4* x; __half2* y;
    switch (blockIdx.y) {
        case 0: x = x0; y = y0; break;
        case 1: x = x1; y = y1; break;
        case 2: x = x2; y = y2; break;
        default: x = x3; y = y3; break;
    }
    float4 v = x[i];
    y[2 * i]     = __floats2half2_rn(v.x, v.y);
    y[2 * i + 1] = __floats2half2_rn(v.z, v.w);
}

__global__ __launch_bounds__(256) void pack_bias(const float* __restrict__ qb,
                                                 const float* __restrict__ kb,
                                                 const float* __restrict__ vb,
                                                 float* __restrict__ dst) {
    int i = blockIdx.x * blockDim.x + threadIdx.x;
    if (i < H) {
        dst[i] = qb[i];
        dst[H + i] = kb[i];
        dst[2 * H + i] = vb[i];
    }
}

// ---------------- single-pass LayerNorm (float2 loads, half2 stores) -------
// H = 1152 floats = 576 float2 per row. Thread t handles chunks t, t+256,
// and t+512 (t < 64). Row cached in registers; fused sum/sumsq with
// warp-shuffle + 8-slot smem reduction. Only 8B loads / 4B stores (widths
// proven safe in prior passing rounds).
#define H2 (H / 2)            // 576

__global__ __launch_bounds__(256) void ln_kernel_h(const float* __restrict__ x,
                                                   const float* __restrict__ g,
                                                   const float* __restrict__ b,
                                                   __half* __restrict__ y) {
    int row = blockIdx.x;
    int tid = threadIdx.x, lane = tid & 31, wid = tid >> 5;
    const float2* xr = (const float2*)(x + (size_t)row * H);

    float2 c0 = xr[tid];
    float2 c1 = xr[tid + 256];
    bool has2 = tid < (H2 - 512);     // tid < 64
    float2 c2 = has2 ? xr[tid + 512] : make_float2(0.f, 0.f);

    float s  = c0.x + c0.y + c1.x + c1.y + c2.x + c2.y;
    float ss = c0.x * c0.x + c0.y * c0.y + c1.x * c1.x + c1.y * c1.y
             + c2.x * c2.x + c2.y * c2.y;

#pragma unroll
    for (int ofs = 16; ofs > 0; ofs >>= 1) {
        s  += __shfl_xor_sync(0xffffffffu, s, ofs);
        ss += __shfl_xor_sync(0xffffffffu, ss, ofs);
    }
    __shared__ float sw[8], ssw[8], stat[2];
    if (lane == 0) { sw[wid] = s; ssw[wid] = ss; }
    __syncthreads();
    if (tid == 0) {
        float t = 0.f, tt = 0.f;
#pragma unroll
        for (int i = 0; i < 8; ++i) { t += sw[i]; tt += ssw[i]; }
        float mu = t * (1.0f / H);
        float var = tt * (1.0f / H) - mu * mu;
        stat[0] = mu;
        stat[1] = rsqrtf(var + LN_EPS);
    }
    __syncthreads();
    float mu = stat[0], inv = stat[1];

    const float2* g2 = (const float2*)g;
    const float2* b2 = (const float2*)b;
    __half* yr = y + (size_t)row * H;

    {
        float2 gv = g2[tid], bv = b2[tid];
        *(__half2*)&yr[tid * 2] = __floats2half2_rn(
            (c0.x - mu) * inv * gv.x + bv.x,
            (c0.y - mu) * inv * gv.y + bv.y);
    }
    {
        int i = tid + 256;
        float2 gv = g2[i], bv = b2[i];
        *(__half2*)&yr[i * 2] = __floats2half2_rn(
            (c1.x - mu) * inv * gv.x + bv.x,
            (c1.y - mu) * inv * gv.y + bv.y);
    }
    if (has2) {
        int i = tid + 512;
        float2 gv = g2[i], bv = b2[i];
        *(__half2*)&yr[i * 2] = __floats2half2_rn(
            (c2.x - mu) * inv * gv.x + bv.x,
            (c2.y - mu) * inv * gv.y + bv.y);
    }
}

// ---------------- document segment ranges (ids are sorted) ----------------
__global__ void doc_ranges(const int* __restrict__ ids, int* __restrict__ segs,
                           int* __restrict__ sege) {
    int i = blockIdx.x * blockDim.x + threadIdx.x;
    if (i >= S) return;
    int d = ids[i];
    int lo = 0, hi = S;
    while (lo < hi) { int mid = (lo + hi) >> 1; if (ids[mid] < d) lo = mid + 1; else hi = mid; }
    segs[i] = lo;
    lo = 0; hi = S;
    while (lo < hi) { int mid = (lo + hi) >> 1; if (ids[mid] <= d) lo = mid + 1; else hi = mid; }
    sege[i] = lo;
}

// ---------------- common mma / ldmatrix ----------------
__device__ __forceinline__ void mma_f16(float* c, const uint32_t* a, const uint32_t* b) {
    asm volatile(
        "mma.sync.aligned.m16n8k16.row.col.f32.f16.f16.f32 "
        "{%0,%1,%2,%3}, {%4,%5,%6,%7}, {%8,%9}, {%0,%1,%2,%3};"
        : "+f"(c[0]), "+f"(c[1]), "+f"(c[2]), "+f"(c[3])
        : "r"(a[0]), "r"(a[1]), "r"(a[2]), "r"(a[3]), "r"(b[0]), "r"(b[1]));
}

__device__ __forceinline__ void ldm_x4(uint32_t* r, uint32_t addr) {
    asm volatile("ldmatrix.sync.aligned.m8n8.x4.shared.b16 {%0,%1,%2,%3}, [%4];"
                 : "=r"(r[0]), "=r"(r[1]), "=r"(r[2]), "=r"(r[3]) : "r"(addr));
}
__device__ __forceinline__ void ldm_x2(uint32_t* r, uint32_t addr) {
    asm volatile("ldmatrix.sync.aligned.m8n8.x2.shared.b16 {%0,%1}, [%2];"
                 : "=r"(r[0]), "=r"(r[1]) : "r"(addr));
}

// ---------------- FP16 tensor-core GEMM (ldmatrix fragments) ---------------
#define BM 128
#define BN 128
#define BKH 32
#define PITCH 40

__device__ __forceinline__ void cp16(void* dst, const void* src, bool valid,
                                     const void* safe) {
    uint32_t d = (uint32_t)__cvta_generic_to_shared(dst);
    const void* s = valid ? src : safe;   // always in-bounds address
    int sz = valid ? 16 : 0;
    asm volatile("cp.async.cg.shared.global [%0], [%1], 16, %2;\n"
                 :: "r"(d), "l"(s), "r"(sz));
}

__global__ __launch_bounds__(256, 2) void gemm_f16(const __half* __restrict__ A,
                                                   const __half* __restrict__ W,
                                                   const float* __restrict__ bias,
                                                   const float* __restrict__ res,
                                                   float* __restrict__ C,
                                                   __half* __restrict__ Ch,
                                                   int M, int N, int K, int epi) {
    __shared__ __half As[2][BM][PITCH];
    __shared__ __half Ws[2][BN][PITCH];

    int tid = threadIdx.x;
    int lane = tid & 31, warp = tid >> 5;
    int wn = warp & 3;
    int wm = warp >> 2;
    int m0 = blockIdx.y * BM;
    int n0 = blockIdx.x * BN;

    int lr = tid >> 1;
    int lc = (tid & 1) * 2;

    const __half* Ab = A + (size_t)m0 * K;

    float acc[4][4][4];
#pragma unroll
    for (int i = 0; i < 4; ++i)
#pragma unroll
        for (int j = 0; j < 4; ++j)
#pragma unroll
            for (int l = 0; l < 4; ++l) acc[i][j][l] = 0.f;

    int nk = (K + BKH - 1) / BKH;

    {
#pragma unroll
        for (int cc = 0; cc < 2; ++cc) {
            int c = lc + cc;
            cp16(&As[0][lr][c * 8], Ab + (size_t)lr * K + c * 8,
                 (c * 8 + 8 <= K), A);
            cp16(&Ws[0][lr][c * 8], W + (size_t)(n0 + lr) * K + c * 8,
                 ((n0 + lr) < N) && (c * 8 + 8 <= K), W);
        }
    }
    asm volatile("cp.async.commit_group;\n" ::: "memory");

    uint32_t aRowOff = (uint32_t)((wm * 64 + (lane & 15)) * PITCH + ((lane >> 4) << 3)) * 2;
    uint32_t bRowOff = (uint32_t)((wn * 32 + (lane & 7)) * PITCH + (((lane >> 3) & 1) << 3)) * 2;

    int fr = lane >> 2;
    int fc = lane & 3;

    for (int t = 0; t < nk; ++t) {
        asm volatile("cp.async.wait_group 0;\n" ::: "memory");
        __syncthreads();

        int st = t & 1;
        if (t + 1 < nk) {
            int ko = (t + 1) * BKH;
#pragma unroll
            for (int cc = 0; cc < 2; ++cc) {
                int c = lc + cc;
                cp16(&As[st ^ 1][lr][c * 8], Ab + (size_t)lr * K + ko + c * 8,
                     (ko + c * 8 + 8 <= K), A);
                cp16(&Ws[st ^ 1][lr][c * 8], W + (size_t)(n0 + lr) * K + ko + c * 8,
                     ((n0 + lr) < N) && (ko + c * 8 + 8 <= K), W);
            }
        }
        asm volatile("cp.async.commit_group;\n" ::: "memory");

        uint32_t aSm = (uint32_t)__cvta_generic_to_shared(&As[st][0][0]) + aRowOff;
        uint32_t bSm = (uint32_t)__cvta_generic_to_shared(&Ws[st][0][0]) + bRowOff;

#pragma unroll
        for (int kk = 0; kk < 2; ++kk) {
            uint32_t kB = (uint32_t)(kk * 16 * 2);
            uint32_t a[4][4], b[4][2];
#pragma unroll
            for (int mt = 0; mt < 4; ++mt)
                ldm_x4(a[mt], aSm + kB + (uint32_t)(mt * 16 * PITCH * 2));
#pragma unroll
            for (int nt = 0; nt < 4; ++nt)
                ldm_x2(b[nt], bSm + kB + (uint32_t)(nt * 8 * PITCH * 2));
#pragma unroll
            for (int mt = 0; mt < 4; ++mt)
#pragma unroll
                for (int nt = 0; nt < 4; ++nt)
                    mma_f16(acc[mt][nt], a[mt], b[nt]);
        }
    }

    // epilogue: column-pair vectorized stores (half2 / float2)
#pragma unroll
    for (int mt = 0; mt < 4; ++mt) {
        int row = m0 + wm * 64 + mt * 16 + fr;
#pragma unroll
        for (int nt = 0; nt < 4; ++nt) {
            int col = n0 + wn * 32 + nt * 8 + fc * 2;
            if (col >= N) continue;           // N even, col even -> col+1 < N too
            float b0 = bias[col];
            float b1 = bias[col + 1];
#pragma unroll
            for (int hh = 0; hh < 2; ++hh) {
                int r = row + (hh ? 8 : 0);
                float v0 = acc[mt][nt][hh * 2 + 0] + b0;
                float v1 = acc[mt][nt][hh * 2 + 1] + b1;
                if (epi == 1) {
                    float u0 = 0.7978845608028654f * (v0 + 0.044715f * v0 * v0 * v0);
                    float e0 = __expf(2.f * u0);
                    v0 = 0.5f * v0 * (2.f - 2.f / (e0 + 1.f));
                    float u1 = 0.7978845608028654f * (v1 + 0.044715f * v1 * v1 * v1);
                    float e1 = __expf(2.f * u1);
                    v1 = 0.5f * v1 * (2.f - 2.f / (e1 + 1.f));
                } else if (epi == 2) {
                    float2 rv = *(const float2*)&res[(size_t)r * N + col];
                    v0 += rv.x;
                    v1 += rv.y;
                }
                if (Ch) {
                    __half2 hv = __floats2half2_rn(v0, v1);
                    *(__half2*)&Ch[(size_t)r * N + col] = hv;
                } else {
                    float2 fv;
                    fv.x = v0; fv.y = v1;
                    *(float2*)&C[(size_t)r * N + col] = fv;
                }
            }
        }
    }
}

// ---------------- tensor-core flash attention (doc-masked) -----------------
#define AQT 64
#define AKT 64
#define QKP 88
#define VTP 72

__global__ __launch_bounds__(128) void attn_mma(const __half* __restrict__ QKV,
                                                const int* __restrict__ segs,
                                                const int* __restrict__ sege,
                                                __half* __restrict__ O) {
    __shared__ __half Qs[AQT][QKP];
    __shared__ __half Ks[AKT][QKP];
    __shared__ __half Vt[HD][VTP];

    int h = blockIdx.y;
    int q0 = blockIdx.x * AQT;
    int tid = threadIdx.x, lane = tid & 31, warp = tid >> 5;
    int fr = lane >> 2, fc = lane & 3;
    const float scale = 0.11785113019775793f;

    const __half* Q = QKV + h * HD;
    const __half* K = QKV + H + h * HD;
    const __half* V = QKV + 2 * H + h * HD;

    {
        uint4 z = make_uint4(0, 0, 0, 0);
        for (int i = tid; i < AQT * QKP / 8; i += 128) ((uint4*)&Qs[0][0])[i] = z;
        for (int i = tid; i < AKT * QKP / 8; i += 128) ((uint4*)&Ks[0][0])[i] = z;
        for (int i = tid; i < HD * VTP / 8; i += 128) ((uint4*)&Vt[0][0])[i] = z;
    }
    __syncthreads();

    for (int i = tid; i < AQT * 9; i += 128) {
        int r = i / 9, c = i - r * 9;
        *(uint4*)&Qs[r][c * 8] = *(const uint4*)&Q[(size_t)(q0 + r) * QKVN + c * 8];
    }

    int rs0[2], rs1[2];
    rs0[0] = segs[q0 + warp * 16 + fr];     rs1[0] = sege[q0 + warp * 16 + fr];
    rs0[1] = segs[q0 + warp * 16 + fr + 8]; rs1[1] = sege[q0 + warp * 16 + fr + 8];
    float m[2] = {-3.0e38f, -3.0e38f};
    float l[2] = {0.f, 0.f};
    float out[9][4];
#pragma unroll
    for (int nt = 0; nt < 9; ++nt)
#pragma unroll
        for (int i = 0; i < 4; ++i) out[nt][i] = 0.f;

    int kstart = segs[q0];
    int kend = sege[q0 + AQT - 1];

    for (int c0 = kstart; c0 < kend; c0 += AKT) {
        int len = min(AKT, kend - c0);
        __syncthreads();

        for (int i = tid; i < len * 9; i += 128) {
            int r = i / 9, c = i - r * 9;
            *(uint4*)&Ks[r][c * 8] = *(const uint4*)&K[(size_t)(c0 + r) * QKVN + c * 8];
        }
        for (int i = tid; i < len * HD; i += 128) {
            int r = i / HD, d = i - r * HD;
            Vt[d][r] = V[(size_t)(c0 + r) * QKVN + d];
        }
        __syncthreads();

        float sc[8][4];
#pragma unroll
        for (int nt = 0; nt < 8; ++nt)
#pragma unroll
            for (int i = 0; i < 4; ++i) sc[nt][i] = 0.f;

#pragma unroll
        for (int kk = 0; kk < 5; ++kk) {
            int kb = kk * 16;
            uint32_t a[4];
            a[0] = *(const uint32_t*)&Qs[warp * 16 + fr][kb + fc * 2];
            a[1] = *(const uint32_t*)&Qs[warp * 16 + fr + 8][kb + fc * 2];
            a[2] = *(const uint32_t*)&Qs[warp * 16 + fr][kb + fc * 2 + 8];
            a[3] = *(const uint32_t*)&Qs[warp * 16 + fr + 8][kb + fc * 2 + 8];
#pragma unroll
            for (int nt = 0; nt < 8; ++nt) {
                uint32_t b[2];
                b[0] = *(const uint32_t*)&Ks[nt * 8 + fr][kb + fc * 2];
                b[1] = *(const uint32_t*)&Ks[nt * 8 + fr][kb + fc * 2 + 8];
                mma_f16(sc[nt], a, b);
            }
        }

        float mx0 = -3.0e38f, mx1 = -3.0e38f;
#pragma unroll
        for (int nt = 0; nt < 8; ++nt) {
            int kg0 = c0 + nt * 8 + fc * 2;
            int kg1 = kg0 + 1;
            sc[nt][0] = (kg0 >= rs0[0] && kg0 < rs1[0]) ? sc[nt][0] * scale : -3.0e38f;
            sc[nt][1] = (kg1 >= rs0[0] && kg1 < rs1[0]) ? sc[nt][1] * scale : -3.0e38f;
            sc[nt][2] = (kg0 >= rs0[1] && kg0 < rs1[1]) ? sc[nt][2] * scale : -3.0e38f;
            sc[nt][3] = (kg1 >= rs0[1] && kg1 < rs1[1]) ? sc[nt][3] * scale : -3.0e38f;
            mx0 = fmaxf(mx0, fmaxf(sc[nt][0], sc[nt][1]));
            mx1 = fmaxf(mx1, fmaxf(sc[nt][2], sc[nt][3]));
        }
#pragma unroll
        for (int ofs = 1; ofs <= 2; ofs <<= 1) {
            mx0 = fmaxf(mx0, __shfl_xor_sync(0xffffffffu, mx0, ofs));
            mx1 = fmaxf(mx1, __shfl_xor_sync(0xffffffffu, mx1, ofs));
        }
        float mnew0 = fmaxf(m[0], mx0);
        float mnew1 = fmaxf(m[1], mx1);
        float corr0 = __expf(m[0] - mnew0);
        float corr1 = __expf(m[1] - mnew1);

        float ps0 = 0.f, ps1 = 0.f;
#pragma unroll
        for (int nt = 0; nt < 8; ++nt) {
            sc[nt][0] = (sc[nt][0] > -1.0e38f) ? __expf(sc[nt][0] - mnew0) : 0.f;
            sc[nt][1] = (sc[nt][1] > -1.0e38f) ? __expf(sc[nt][1] - mnew0) : 0.f;
            sc[nt][2] = (sc[nt][2] > -1.0e38f) ? __expf(sc[nt][2] - mnew1) : 0.f;
            sc[nt][3] = (sc[nt][3] > -1.0e38f) ? __expf(sc[nt][3] - mnew1) : 0.f;
            ps0 += sc[nt][0] + sc[nt][1];
            ps1 += sc[nt][2] + sc[nt][3];
        }
#pragma unroll
        for (int ofs = 1; ofs <= 2; ofs <<= 1) {
            ps0 += __shfl_xor_sync(0xffffffffu, ps0, ofs);
            ps1 += __shfl_xor_sync(0xffffffffu, ps1, ofs);
        }
        l[0] = l[0] * corr0 + ps0;
        l[1] = l[1] * corr1 + ps1;
        m[0] = mnew0;
        m[1] = mnew1;

#pragma unroll
        for (int nt = 0; nt < 9; ++nt) {
            out[nt][0] *= corr0; out[nt][1] *= corr0;
            out[nt][2] *= corr1; out[nt][3] *= corr1;
        }
        uint32_t pr0[8], pr1[8];
#pragma unroll
        for (int nt = 0; nt < 8; ++nt) {
            __half2 h0 = __floats2half2_rn(sc[nt][0], sc[nt][1]);
            __half2 h1 = __floats2half2_rn(sc[nt][2], sc[nt][3]);
            pr0[nt] = *(uint32_t*)&h0;
            pr1[nt] = *(uint32_t*)&h1;
        }
#pragma unroll
        for (int j = 0; j < 4; ++j) {
            uint32_t a[4] = {pr0[2 * j], pr1[2 * j], pr0[2 * j + 1], pr1[2 * j + 1]};
            int kb = j * 16;
#pragma unroll
            for (int nt = 0; nt < 9; ++nt) {
                uint32_t b[2];
                b[0] = *(const uint32_t*)&Vt[nt * 8 + fr][kb + fc * 2];
                b[1] = *(const uint32_t*)&Vt[nt * 8 + fr][kb + fc * 2 + 8];
                mma_f16(out[nt], a, b);
            }
        }
    }

    float inv0 = 1.f / l[0];
    float inv1 = 1.f / l[1];
    size_t base0 = (size_t)(q0 + warp * 16 + fr) * H + h * HD;
    size_t base1 = (size_t)(q0 + warp * 16 + fr + 8) * H + h * HD;
#pragma unroll
    for (int nt = 0; nt < 9; ++nt) {
        int col = nt * 8 + fc * 2;
        __half2 o0 = __floats2half2_rn(out[nt][0] * inv0, out[nt][1] * inv0);
        __half2 o1 = __floats2half2_rn(out[nt][2] * inv1, out[nt][3] * inv1);
        *(__half2*)&O[base0 + col] = o0;
        *(__half2*)&O[base1 + col] = o1;
    }
}

// ---------------- launch ----------------
extern "C" void kernel_launch(void* const* d_in, const int* in_sizes, int n_in,
                              void* d_out, int out_size) {
    const float* hs    = (const float*)d_in[0];
    const int*   doc   = (const int*)d_in[1];
    const float* q_w   = (const float*)d_in[2];
    const float* q_b   = (const float*)d_in[3];
    const float* k_w   = (const float*)d_in[4];
    const float* k_b   = (const float*)d_in[5];
    const float* v_w   = (const float*)d_in[6];
    const float* v_b   = (const float*)d_in[7];
    const float* o_w   = (const float*)d_in[8];
    const float* o_b   = (const float*)d_in[9];
    const float* ln1_g = (const float*)d_in[10];
    const float* ln1_b = (const float*)d_in[11];
    const float* ln2_g = (const float*)d_in[12];
    const float* ln2_b = (const float*)d_in[13];
    const float* fc1_w = (const float*)d_in[14];
    const float* fc1_b = (const float*)d_in[15];
    const float* fc2_w = (const float*)d_in[16];
    const float* fc2_b = (const float*)d_in[17];
    float* out = (float*)d_out;

    __half *xnh, *qkvh, *attnh, *yh, *ffh;
    __half *wqkvh, *owh, *fc1h, *fc2h;
    float *hid, *bqkv;
    int *segs, *sege;
    cudaGetSymbolAddress((void**)&xnh,   g_xnh);
    cudaGetSymbolAddress((void**)&qkvh,  g_qkvh);
    cudaGetSymbolAddress((void**)&attnh, g_attnh);
    cudaGetSymbolAddress((void**)&hid,   g_hid);
    cudaGetSymbolAddress((void**)&yh,    g_yh);
    cudaGetSymbolAddress((void**)&ffh,   g_ffh);
    cudaGetSymbolAddress((void**)&wqkvh, g_wqkvh);
    cudaGetSymbolAddress((void**)&owh,   g_owh);
    cudaGetSymbolAddress((void**)&fc1h,  g_fc1h);
    cudaGetSymbolAddress((void**)&fc2h,  g_fc2h);
    cudaGetSymbolAddress((void**)&bqkv,  g_bqkv);
    cudaGetSymbolAddress((void**)&segs,  g_segs);
    cudaGetSymbolAddress((void**)&sege,  g_sege);

    int nHH4 = H * H / 4;
    int nHF4 = H * FF / 4;
    cvt_f2h4<<<dim3((nHH4 + 255) / 256, 4), 256>>>(
        (const float4*)q_w, (const float4*)k_w, (const float4*)v_w, (const float4*)o_w,
        (__half2*)wqkvh, (__half2*)(wqkvh + (size_t)H * H),
        (__half2*)(wqkvh + (size_t)2 * H * H), (__half2*)owh, nHH4);
    cvt_f2h<<<(nHF4 + 255) / 256, 256>>>((const float4*)fc1_w, (__half2*)fc1h, nHF4);
    cvt_f2h<<<(nHF4 + 255) / 256, 256>>>((const float4*)fc2_w, (__half2*)fc2h, nHF4);
    pack_bias<<<(H + 255) / 256, 256>>>(q_b, k_b, v_b, bqkv);

    dim3 gQKV(QKVN / BN, S / BM);            // (27, 32)
    dim3 gH(H / BN, S / BM);                 // (9, 32)
    dim3 gF((FF + BN - 1) / BN, S / BM);     // (34, 32)

    ln_kernel_h<<<S, 256>>>(hs, ln1_g, ln1_b, xnh);
    doc_ranges<<<(S + 255) / 256, 256>>>(doc, segs, sege);

    gemm_f16<<<gQKV, 256>>>(xnh, wqkvh, bqkv, nullptr, nullptr, qkvh, S, QKVN, H, 0);

    attn_mma<<<dim3(S / AQT, NH), 128>>>(qkvh, segs, sege, attnh);

    gemm_f16<<<gH, 256>>>(attnh, owh, o_b, hs, hid, nullptr, S, H, H, 2);

    ln_kernel_h<<<S, 256>>>(hid, ln2_g, ln2_b, yh);

    gemm_f16<<<gF, 256>>>(yh, fc1h, fc1_b, nullptr, nullptr, ffh, S, FF, H, 1);
    gemm_f16<<<gH, 256>>>(ffh, fc2h, fc2_b, hid, out, nullptr, S, H, FF, 2);
}